// round 3
// baseline (speedup 1.0000x reference)
#include <cuda_runtime.h>

#define B_    128
#define NPG   12
#define EPG   132
#define E_TOT 16896
#define NT    1536
#define NC    1056   // 512 jf | 512 ju | 32 fl

__device__ float d_W[192 * NC];
__device__ float d_gc[B_ * NC];
__device__ float d_fc[E_TOT * NC];
__device__ float d_fv[E_TOT * 256];
__device__ float d_uv[E_TOT * 256];
__device__ float d_flag[E_TOT];
__device__ float d_if[NT * 16];
__device__ float d_iu[NT * 16];

__device__ __forceinline__ unsigned long long pk2(float lo, float hi) {
    unsigned long long r;
    asm("mov.b64 %0, {%1, %2};" : "=l"(r) : "f"(lo), "f"(hi));
    return r;
}
__device__ __forceinline__ void fma2(unsigned long long& d, unsigned long long a, unsigned long long b) {
    asm("fma.rn.f32x2 %0, %1, %2, %0;" : "+l"(d) : "l"(a), "l"(b));
}
__device__ __forceinline__ void up2(unsigned long long v, float& lo, float& hi) {
    asm("mov.b64 {%0, %1}, %2;" : "=f"(lo), "=f"(hi) : "l"(v));
}
__device__ __forceinline__ int revloc(int ee) {
    int s = ee / 11, dd = ee - s * 11;
    int d = dd + (dd >= s);
    return d * 11 + s - (s > d);
}

// ---- K1: pack [W_jf|W_ju|W_fl] into d_W[k][j] ----
__global__ void pack_w(const float* __restrict__ Wjf, const float* __restrict__ Wju,
                       const float* __restrict__ Wfl) {
    int i = blockIdx.x * blockDim.x + threadIdx.x;
    if (i >= 192 * NC) return;
    int k = i / NC, j = i - k * NC;
    d_W[i] = (j < 512) ? Wjf[k * 512 + j]
           : (j < 1024) ? Wju[k * 512 + j - 512]
           : Wfl[k * 32 + j - 1024];
}

// ---- K2: per-graph part + bias ----
__global__ void gc_k(const float* __restrict__ gf, const float* __restrict__ bjf,
                     const float* __restrict__ bju, const float* __restrict__ bfl) {
    int i = blockIdx.x * blockDim.x + threadIdx.x;
    if (i >= B_ * NC) return;
    int g = i / NC, j = i - g * NC;
    float acc = (j < 512) ? bjf[j] : (j < 1024 ? bju[j - 512] : bfl[j - 1024]);
    const float* gr = gf + g * 64;
#pragma unroll 8
    for (int k = 0; k < 64; ++k) acc += gr[k] * d_W[(128 + k) * NC + j];
    d_gc[i] = acc;
}

// ---- K3: node linears ----
__global__ void node_k(const float* __restrict__ nf, const float* __restrict__ gf,
                       const float* __restrict__ Wif, const float* __restrict__ bif,
                       const float* __restrict__ Wiu, const float* __restrict__ biu) {
    __shared__ float xn[128];
    int n = blockIdx.x, t = threadIdx.x;
    int g = n / NPG;
    for (int i = t; i < 128; i += 32)
        xn[i] = (i < 64) ? nf[n * 64 + i] : gf[g * 64 + i - 64];
    __syncthreads();
    const float* W = (t < 16) ? Wif : Wiu;
    int col = t & 15;
    float acc = (t < 16) ? bif[col] : biu[col];
#pragma unroll 8
    for (int k = 0; k < 128; ++k) acc += xn[k] * W[k * 16 + col];
    if (t < 16) d_if[n * 16 + col] = acc;
    else        d_iu[n * 16 + col] = acc;
}

// ---- K4: main GEMM d_fc = ef @ W[0:128] + gc ----
__global__ void gemm_k(const float* __restrict__ ef) {
    __shared__ __align__(16) float As[64][64];
    __shared__ __align__(16) float Bs[64][64];
    int bn = blockIdx.x * 64, bm = blockIdx.y * 64;
    int t = threadIdx.x, tx = t & 15, ty = t >> 4;
    unsigned long long c[4][2];
#pragma unroll
    for (int q = 0; q < 4; ++q) { c[q][0] = 0ULL; c[q][1] = 0ULL; }
    for (int kk = 0; kk < 128; kk += 64) {
#pragma unroll
        for (int i = 0; i < 4; ++i) {
            int idx = i * 256 + t, row = idx >> 4, c4 = idx & 15;
            *(float4*)&As[row][c4 * 4] = *(const float4*)(ef + (bm + row) * 128 + kk + c4 * 4);
        }
#pragma unroll
        for (int i = 0; i < 4; ++i) {
            int idx = i * 256 + t, k = idx >> 4, c4 = idx & 15;
            int col = bn + c4 * 4;
            float4 v = make_float4(0.f, 0.f, 0.f, 0.f);
            if (col < NC) v = *(const float4*)(d_W + (kk + k) * NC + col);
            *(float4*)&Bs[k][c4 * 4] = v;
        }
        __syncthreads();
#pragma unroll 16
        for (int k = 0; k < 64; ++k) {
            ulonglong2 b2 = *(const ulonglong2*)&Bs[k][tx * 4];
#pragma unroll
            for (int q = 0; q < 4; ++q) {
                float av = As[ty * 4 + q][k];
                unsigned long long aa = pk2(av, av);
                fma2(c[q][0], aa, b2.x);
                fma2(c[q][1], aa, b2.y);
            }
        }
        __syncthreads();
    }
    int col = bn + tx * 4;
    if (col < NC) {
#pragma unroll
        for (int q = 0; q < 4; ++q) {
            int row = bm + ty * 4 + q;
            int g = row / EPG;
            float4 gc4 = *(const float4*)(d_gc + g * NC + col);
            float o0, o1, o2, o3;
            up2(c[q][0], o0, o1); up2(c[q][1], o2, o3);
            float4 ov = make_float4(o0 + gc4.x, o1 + gc4.y, o2 + gc4.z, o3 + gc4.w);
            *(float4*)(d_fc + row * NC + col) = ov;
        }
    }
}

// ---- K5: einsum fv[e]=fc[e]@fc[rev]^T (jf part) and uv (ju part) ----
__global__ void einsum_k() {
    __shared__ __align__(16) float sE[4 * 1056];  // [le][mat*528 + a*33 + m]
    __shared__ __align__(16) float sR[4 * 1024];  // [le][mat*512 + m*16 + b]
    int t = threadIdx.x, bE = blockIdx.x * 4;
#pragma unroll
    for (int i = 0; i < 16; ++i) {
        int idx = i * 128 + t;
        int side = idx >> 10, rem = idx & 1023;
        int le = rem >> 8, j = (rem & 255) * 4;
        int e = bE + le;
        int g = e / EPG, ee = e - g * EPG;
        int mat = j >> 9, w = j & 511, a2 = w >> 5, m = w & 31;
        if (side == 0) {
            float4 v = *(const float4*)(d_fc + e * NC + j);
            float* p = sE + le * 1056 + mat * 528 + a2 * 33 + m;
            p[0] = v.x; p[1] = v.y; p[2] = v.z; p[3] = v.w;
        } else {
            int r = g * EPG + revloc(ee);
            float4 v = *(const float4*)(d_fc + r * NC + j);
            float* p = sR + le * 1024 + mat * 512 + m * 16 + a2;
            p[0] = v.x; p[16] = v.y; p[32] = v.z; p[48] = v.w;
        }
    }
    __syncthreads();
    int le = t >> 5, lane = t & 31, a = lane & 15, half = lane >> 4;
    int e = bE + le;
#pragma unroll
    for (int mat = 0; mat < 2; ++mat) {
        const float* Er = sE + le * 1056 + mat * 528 + a * 33;
        const float* Rr = sR + le * 1024 + mat * 512 + half * 8;
        float acc[8];
#pragma unroll
        for (int j = 0; j < 8; ++j) acc[j] = 0.f;
#pragma unroll
        for (int m = 0; m < 32; ++m) {
            float va = Er[m];
            float4 r0 = *(const float4*)(Rr + m * 16);
            float4 r1 = *(const float4*)(Rr + m * 16 + 4);
            acc[0] += va * r0.x; acc[1] += va * r0.y; acc[2] += va * r0.z; acc[3] += va * r0.w;
            acc[4] += va * r1.x; acc[5] += va * r1.y; acc[6] += va * r1.z; acc[7] += va * r1.w;
        }
        float* op = (mat ? d_uv : d_fv) + e * 256 + a * 16 + half * 8;
        *(float4*)op = make_float4(acc[0], acc[1], acc[2], acc[3]);
        *(float4*)(op + 4) = make_float4(acc[4], acc[5], acc[6], acc[7]);
    }
}

// ---- K6: gumbel hard flag ----
__global__ void flag_k(const float* __restrict__ noise, const float* __restrict__ Wc,
                       const float* __restrict__ bc) {
    int t = threadIdx.x, lane = t & 31;
    int e = blockIdx.x * 8 + (t >> 5);
    int g = e / EPG, ee = e - g * EPG;
    int r = g * EPG + revloc(ee);
    float p = d_fc[e * NC + 1024 + lane] * d_fc[r * NC + 1024 + lane];
    float l0 = p * Wc[lane * 2 + 0];
    float l1 = p * Wc[lane * 2 + 1];
#pragma unroll
    for (int m = 16; m > 0; m >>= 1) {
        l0 += __shfl_xor_sync(0xffffffffu, l0, m);
        l1 += __shfl_xor_sync(0xffffffffu, l1, m);
    }
    if (lane == 0) {
        int mn = min(e, r);
        float y0 = l0 + bc[0] + noise[2 * mn];
        float y1 = l1 + bc[1] + noise[2 * mn + 1];
        d_flag[e] = (y0 >= y1) ? 1.f : 0.f;
    }
}

// ---- K7: BP, one CTA per graph ----
__global__ void __launch_bounds__(256) bp_k(float* __restrict__ out) {
    __shared__ float sA[2112], sB[2112], uA[2112], uB[2112];
    __shared__ float s_mm[192], s_um[192], s_if[192], s_iu[192], s_fl[EPG];
    int g = blockIdx.x, t = threadIdx.x;
    for (int i = t; i < 2112; i += 256) { sA[i] = 0.f; sB[i] = 0.f; uA[i] = 0.f; uB[i] = 0.f; }
    for (int i = t; i < 192; i += 256) {
        s_mm[i] = 0.f; s_um[i] = 0.f;
        s_if[i] = d_if[g * 192 + i];
        s_iu[i] = d_iu[g * 192 + i];
    }
    for (int i = t; i < EPG; i += 256) s_fl[i] = d_flag[g * EPG + i];
    __syncthreads();

    for (int it = 0; it < NPG; ++it) {
        const float* om = (it & 1) ? sB : sA;
        const float* ou = (it & 1) ? uB : uA;
        float* nm = (it & 1) ? sA : sB;
        float* nu = (it & 1) ? uA : uB;
        for (int idx = t; idx < 2112; idx += 256) {
            int e = idx >> 4, a = idx & 15;
            unsigned mask = (t & 16) ? 0xFFFF0000u : 0x0000FFFFu;
            if (s_fl[e] == 0.f) continue;
            int s = e / 11;
            int rev = revloc(e);
            int ge = g * EPG + e;
            const float4* fvp = (const float4*)(d_fv + ge * 256 + a * 16);
            float m[16], mx = -1e30f;
#pragma unroll
            for (int q = 0; q < 4; ++q) {
                float4 fv4 = fvp[q];
                float vals[4] = {fv4.x, fv4.y, fv4.z, fv4.w};
#pragma unroll
                for (int j = 0; j < 4; ++j) {
                    int b = q * 4 + j;
                    float agg = s_mm[s * 16 + b] - om[rev * 16 + b] + s_if[s * 16 + b];
                    m[b] = vals[j] + agg;
                    mx = fmaxf(mx, m[b]);
                }
            }
            float se = 0.f;
#pragma unroll
            for (int b = 0; b < 16; ++b) se += __expf(m[b] - mx);
            float lse = mx + __logf(se);
            // log-softmax over a (group of 16 lanes)
            float gm = lse;
#pragma unroll
            for (int w = 8; w > 0; w >>= 1) gm = fmaxf(gm, __shfl_xor_sync(mask, gm, w));
            float gs = __expf(lse - gm);
#pragma unroll
            for (int w = 8; w > 0; w >>= 1) gs += __shfl_xor_sync(mask, gs, w);
            float GL = gm + __logf(gs);
            nm[e * 16 + a] = lse - GL;
            // utility message
            const float4* uvp = (const float4*)(d_uv + ge * 256 + a * 16);
            float acc = 0.f;
#pragma unroll
            for (int q = 0; q < 4; ++q) {
                float4 uv4 = uvp[q];
                float vals[4] = {uv4.x, uv4.y, uv4.z, uv4.w};
#pragma unroll
                for (int j = 0; j < 4; ++j) {
                    int b = q * 4 + j;
                    float util = s_um[s * 16 + b] - ou[rev * 16 + b] + s_iu[s * 16 + b];
                    acc += (vals[j] + util) * __expf(m[b] - lse);
                }
            }
            nu[e * 16 + a] = acc;
        }
        __syncthreads();
        if (t < 192) {
            int n = t >> 4, b = t & 15;
            float am = 0.f, au = 0.f;
#pragma unroll
            for (int s2 = 0; s2 < NPG; ++s2) {
                if (s2 == n) continue;
                int ee = s2 * 11 + n - (n > s2);
                am += nm[ee * 16 + b];
                au += nu[ee * 16 + b];
            }
            s_mm[t] = am; s_um[t] = au;
        }
        __syncthreads();
    }
    if (t < 16) out[g * 16 + t] = s_um[t] + s_iu[t];
}

extern "C" void kernel_launch(void* const* d_in, const int* in_sizes, int n_in,
                              void* d_out, int out_size) {
    const float* ef   = (const float*)d_in[0];
    const float* nf   = (const float*)d_in[1];
    const float* gf   = (const float*)d_in[2];
    const float* gn   = (const float*)d_in[7];
    const float* Wjf  = (const float*)d_in[8];
    const float* bjf  = (const float*)d_in[9];
    const float* Wif  = (const float*)d_in[10];
    const float* bif  = (const float*)d_in[11];
    const float* Wju  = (const float*)d_in[12];
    const float* bju  = (const float*)d_in[13];
    const float* Wiu  = (const float*)d_in[14];
    const float* biu  = (const float*)d_in[15];
    const float* Wfl  = (const float*)d_in[16];
    const float* bfl  = (const float*)d_in[17];
    const float* Wcls = (const float*)d_in[18];
    const float* bcls = (const float*)d_in[19];
    float* out = (float*)d_out;

    pack_w<<<(192 * NC + 255) / 256, 256>>>(Wjf, Wju, Wfl);
    gc_k<<<(B_ * NC + 255) / 256, 256>>>(gf, bjf, bju, bfl);
    node_k<<<NT, 32>>>(nf, gf, Wif, bif, Wiu, biu);
    gemm_k<<<dim3(17, 264), 256>>>(ef);
    einsum_k<<<E_TOT / 4, 128>>>();
    flag_k<<<E_TOT / 8, 256>>>(gn, Wcls, bcls);
    bp_k<<<B_, 256>>>(out);
}

// round 4
// speedup vs baseline: 1.5034x; 1.5034x over previous
#include <cuda_runtime.h>

#define B_    128
#define NPG   12
#define EPG   132
#define E_TOT 16896
#define NT    1536
#define NC    1056   // 512 jf | 512 ju | 32 fl (in d_W / d_gc)

__device__ float d_W[192 * NC];
__device__ float d_gc[B_ * NC];
__device__ float d_fc[E_TOT * 1024];   // jf|ju rows, only flag-1 edges valid
__device__ float d_flv[E_TOT * 32];    // fl linear output
__device__ float d_fv[E_TOT * 256];
__device__ float d_uv[E_TOT * 256];
__device__ float d_flag[E_TOT];
__device__ float d_if[NT * 16];
__device__ float d_iu[NT * 16];
__device__ int   d_cnt;
__device__ int   d_list[E_TOT];

__device__ __forceinline__ unsigned long long pk2(float lo, float hi) {
    unsigned long long r;
    asm("mov.b64 %0, {%1, %2};" : "=l"(r) : "f"(lo), "f"(hi));
    return r;
}
__device__ __forceinline__ void fma2(unsigned long long& d, unsigned long long a, unsigned long long b) {
    asm("fma.rn.f32x2 %0, %1, %2, %0;" : "+l"(d) : "l"(a), "l"(b));
}
__device__ __forceinline__ void up2(unsigned long long v, float& lo, float& hi) {
    asm("mov.b64 {%0, %1}, %2;" : "=f"(lo), "=f"(hi) : "l"(v));
}
__device__ __forceinline__ int revloc(int ee) {
    int s = ee / 11, dd = ee - s * 11;
    int d = dd + (dd >= s);
    return d * 11 + s - (s > d);
}

// ---- K1: pack [W_jf|W_ju|W_fl] into d_W[k][j] ----
__global__ void pack_w(const float* __restrict__ Wjf, const float* __restrict__ Wju,
                       const float* __restrict__ Wfl) {
    int i = blockIdx.x * blockDim.x + threadIdx.x;
    if (i >= 192 * NC) return;
    int k = i / NC, j = i - k * NC;
    d_W[i] = (j < 512) ? Wjf[k * 512 + j]
           : (j < 1024) ? Wju[k * 512 + j - 512]
           : Wfl[k * 32 + j - 1024];
}

// ---- K2: per-graph part + bias ----
__global__ void gc_k(const float* __restrict__ gf, const float* __restrict__ bjf,
                     const float* __restrict__ bju, const float* __restrict__ bfl) {
    int i = blockIdx.x * blockDim.x + threadIdx.x;
    if (i >= B_ * NC) return;
    int g = i / NC, j = i - g * NC;
    float acc = (j < 512) ? bjf[j] : (j < 1024 ? bju[j - 512] : bfl[j - 1024]);
    const float* gr = gf + g * 64;
#pragma unroll 8
    for (int k = 0; k < 64; ++k) acc += gr[k] * d_W[(128 + k) * NC + j];
    d_gc[i] = acc;
}

// ---- K3: node linears ----
__global__ void node_k(const float* __restrict__ nf, const float* __restrict__ gf,
                       const float* __restrict__ Wif, const float* __restrict__ bif,
                       const float* __restrict__ Wiu, const float* __restrict__ biu) {
    __shared__ float xn[128];
    int n = blockIdx.x, t = threadIdx.x;
    int g = n / NPG;
    for (int i = t; i < 128; i += 32)
        xn[i] = (i < 64) ? nf[n * 64 + i] : gf[g * 64 + i - 64];
    __syncthreads();
    const float* W = (t < 16) ? Wif : Wiu;
    int col = t & 15;
    float acc = (t < 16) ? bif[col] : biu[col];
#pragma unroll 8
    for (int k = 0; k < 128; ++k) acc += xn[k] * W[k * 16 + col];
    if (t < 16) d_if[n * 16 + col] = acc;
    else        d_iu[n * 16 + col] = acc;
}

// ---- K4: fl linear for ALL edges (32 cols) ----
__global__ void flv_k(const float* __restrict__ ef, const float* __restrict__ Wfl) {
    __shared__ float Ws[128 * 32];
    int t = threadIdx.x;
    for (int i = t; i < 4096; i += 256) Ws[i] = Wfl[i];
    __syncthreads();
    int r = t >> 1, half = t & 1;
    int e = blockIdx.x * 128 + r;
    int g = e / EPG;
    int co = half * 16;
    unsigned long long acc[8];
#pragma unroll
    for (int c = 0; c < 8; ++c)
        acc[c] = pk2(d_gc[g * NC + 1024 + co + c * 2], d_gc[g * NC + 1024 + co + c * 2 + 1]);
    const float4* ep = (const float4*)(ef + e * 128);
#pragma unroll 4
    for (int k4 = 0; k4 < 32; ++k4) {
        float4 ev = ep[k4];
        float evs[4] = {ev.x, ev.y, ev.z, ev.w};
#pragma unroll
        for (int j = 0; j < 4; ++j) {
            int k = k4 * 4 + j;
            unsigned long long aa = pk2(evs[j], evs[j]);
            const float4* wr = (const float4*)(Ws + k * 32 + co);
            float4 w0 = wr[0], w1 = wr[1], w2 = wr[2], w3 = wr[3];
            fma2(acc[0], aa, pk2(w0.x, w0.y)); fma2(acc[1], aa, pk2(w0.z, w0.w));
            fma2(acc[2], aa, pk2(w1.x, w1.y)); fma2(acc[3], aa, pk2(w1.z, w1.w));
            fma2(acc[4], aa, pk2(w2.x, w2.y)); fma2(acc[5], aa, pk2(w2.z, w2.w));
            fma2(acc[6], aa, pk2(w3.x, w3.y)); fma2(acc[7], aa, pk2(w3.z, w3.w));
        }
    }
#pragma unroll
    for (int c = 0; c < 8; ++c) {
        float lo, hi;
        up2(acc[c], lo, hi);
        d_flv[e * 32 + co + c * 2] = lo;
        d_flv[e * 32 + co + c * 2 + 1] = hi;
    }
    if (blockIdx.x == 0 && t == 0) d_cnt = 0;
}

// ---- K5: gumbel hard flag + compaction ----
__global__ void flagc_k(const float* __restrict__ noise, const float* __restrict__ Wc,
                        const float* __restrict__ bc) {
    int t = threadIdx.x, lane = t & 31;
    int e = blockIdx.x * 8 + (t >> 5);
    int g = e / EPG, ee = e - g * EPG;
    int r = g * EPG + revloc(ee);
    float p = d_flv[e * 32 + lane] * d_flv[r * 32 + lane];
    float l0 = p * Wc[lane * 2 + 0];
    float l1 = p * Wc[lane * 2 + 1];
#pragma unroll
    for (int m = 16; m > 0; m >>= 1) {
        l0 += __shfl_xor_sync(0xffffffffu, l0, m);
        l1 += __shfl_xor_sync(0xffffffffu, l1, m);
    }
    if (lane == 0) {
        int mn = min(e, r);
        float y0 = l0 + bc[0] + noise[2 * mn];
        float y1 = l1 + bc[1] + noise[2 * mn + 1];
        float f = (y0 >= y1) ? 1.f : 0.f;
        d_flag[e] = f;
        if (f != 0.f) {
            int s = atomicAdd(&d_cnt, 1);
            d_list[s] = e;
        }
    }
}

// ---- K6: gathered GEMM over flag-1 edges: d_fc[e] = ef[e] @ W[:,0:1024] + gc ----
__global__ void __launch_bounds__(256, 2) gemm_k(const float* __restrict__ ef) {
    __shared__ int sIdx[128];
    __shared__ __align__(16) float As[32][128];
    __shared__ __align__(16) float Bs[32][128];
    int cnt = d_cnt;
    int bm = blockIdx.y * 128;
    if (bm >= cnt) return;
    int bn = blockIdx.x * 128;
    int t = threadIdx.x;
    if (t < 128) sIdx[t] = d_list[min(bm + t, E_TOT - 1)];
    __syncthreads();
    int tx = t & 15, ty = t >> 4;
    unsigned long long c[8][4];
#pragma unroll
    for (int q = 0; q < 8; ++q)
#pragma unroll
        for (int j = 0; j < 4; ++j) c[q][j] = 0ULL;

    for (int kk = 0; kk < 128; kk += 32) {
#pragma unroll
        for (int i = 0; i < 4; ++i) {
            int idx = i * 256 + t;
            int m = idx & 127, k4 = idx >> 7;
            float4 v = *(const float4*)(ef + sIdx[m] * 128 + kk + k4 * 4);
            As[k4 * 4 + 0][m] = v.x; As[k4 * 4 + 1][m] = v.y;
            As[k4 * 4 + 2][m] = v.z; As[k4 * 4 + 3][m] = v.w;
        }
#pragma unroll
        for (int i = 0; i < 4; ++i) {
            int idx = i * 256 + t;
            int n4 = idx & 31, k = idx >> 5;
            *(float4*)&Bs[k][n4 * 4] = *(const float4*)(d_W + (kk + k) * NC + bn + n4 * 4);
        }
        __syncthreads();
#pragma unroll
        for (int k = 0; k < 32; ++k) {
            float4 b0 = *(const float4*)&Bs[k][tx * 8];
            float4 b1 = *(const float4*)&Bs[k][tx * 8 + 4];
            unsigned long long bb0 = pk2(b0.x, b0.y), bb1 = pk2(b0.z, b0.w);
            unsigned long long bb2 = pk2(b1.x, b1.y), bb3 = pk2(b1.z, b1.w);
            float4 a0 = *(const float4*)&As[k][ty * 8];
            float4 a1 = *(const float4*)&As[k][ty * 8 + 4];
            float av[8] = {a0.x, a0.y, a0.z, a0.w, a1.x, a1.y, a1.z, a1.w};
#pragma unroll
            for (int q = 0; q < 8; ++q) {
                unsigned long long aa = pk2(av[q], av[q]);
                fma2(c[q][0], aa, bb0); fma2(c[q][1], aa, bb1);
                fma2(c[q][2], aa, bb2); fma2(c[q][3], aa, bb3);
            }
        }
        __syncthreads();
    }
#pragma unroll
    for (int q = 0; q < 8; ++q) {
        int slot = bm + ty * 8 + q;
        if (slot < cnt) {
            int e = sIdx[ty * 8 + q];
            int g = e / EPG;
            int col = bn + tx * 8;
            float4 g0 = *(const float4*)(d_gc + g * NC + col);
            float4 g1 = *(const float4*)(d_gc + g * NC + col + 4);
            float o0, o1, o2, o3, o4, o5, o6, o7;
            up2(c[q][0], o0, o1); up2(c[q][1], o2, o3);
            up2(c[q][2], o4, o5); up2(c[q][3], o6, o7);
            float4 w0 = make_float4(o0 + g0.x, o1 + g0.y, o2 + g0.z, o3 + g0.w);
            float4 w1 = make_float4(o4 + g1.x, o5 + g1.y, o6 + g1.z, o7 + g1.w);
            *(float4*)(d_fc + e * 1024 + col) = w0;
            *(float4*)(d_fc + e * 1024 + col + 4) = w1;
        }
    }
}

// ---- K7: einsum over flag-1 edges ----
__global__ void einsum_k() {
    __shared__ __align__(16) float sE[4 * 1056];  // [le][mat*528 + a*33 + m]
    __shared__ __align__(16) float sR[4 * 1024];  // [le][mat*512 + m*16 + b]
    __shared__ int sID[4];
    int cnt = d_cnt;
    int base = blockIdx.x * 4;
    if (base >= cnt) return;
    int t = threadIdx.x;
    if (t < 4) sID[t] = d_list[min(base + t, E_TOT - 1)];
    __syncthreads();
#pragma unroll
    for (int i = 0; i < 16; ++i) {
        int idx = i * 128 + t;
        int side = idx >> 10, rem = idx & 1023;
        int le = rem >> 8, j = (rem & 255) * 4;
        int e = sID[le];
        int mat = j >> 9, w = j & 511, a2 = w >> 5, m = w & 31;
        if (side == 0) {
            float4 v = *(const float4*)(d_fc + e * 1024 + j);
            float* p = sE + le * 1056 + mat * 528 + a2 * 33 + m;
            p[0] = v.x; p[1] = v.y; p[2] = v.z; p[3] = v.w;
        } else {
            int g = e / EPG, ee = e - g * EPG;
            int r = g * EPG + revloc(ee);
            float4 v = *(const float4*)(d_fc + r * 1024 + j);
            float* p = sR + le * 1024 + mat * 512 + m * 16 + a2;
            p[0] = v.x; p[16] = v.y; p[32] = v.z; p[48] = v.w;
        }
    }
    __syncthreads();
    int le = t >> 5, lane = t & 31, a = lane & 15, half = lane >> 4;
    if (base + le >= cnt) return;
    int e = sID[le];
#pragma unroll
    for (int mat = 0; mat < 2; ++mat) {
        const float* Er = sE + le * 1056 + mat * 528 + a * 33;
        const float* Rr = sR + le * 1024 + mat * 512 + half * 8;
        unsigned long long acc[4];
#pragma unroll
        for (int j = 0; j < 4; ++j) acc[j] = 0ULL;
#pragma unroll
        for (int m = 0; m < 32; ++m) {
            float va = Er[m];
            unsigned long long aa = pk2(va, va);
            float4 r0 = *(const float4*)(Rr + m * 16);
            float4 r1 = *(const float4*)(Rr + m * 16 + 4);
            fma2(acc[0], aa, pk2(r0.x, r0.y)); fma2(acc[1], aa, pk2(r0.z, r0.w));
            fma2(acc[2], aa, pk2(r1.x, r1.y)); fma2(acc[3], aa, pk2(r1.z, r1.w));
        }
        float o0, o1, o2, o3, o4, o5, o6, o7;
        up2(acc[0], o0, o1); up2(acc[1], o2, o3);
        up2(acc[2], o4, o5); up2(acc[3], o6, o7);
        float* op = (mat ? d_uv : d_fv) + e * 256 + a * 16 + half * 8;
        *(float4*)op = make_float4(o0, o1, o2, o3);
        *(float4*)(op + 4) = make_float4(o4, o5, o6, o7);
    }
}

// ---- K8: BP, one CTA per graph ----
__global__ void __launch_bounds__(256) bp_k(float* __restrict__ out) {
    __shared__ float sA[2112], sB[2112], uA[2112], uB[2112];
    __shared__ float s_mm[192], s_um[192], s_if[192], s_iu[192], s_fl[EPG];
    int g = blockIdx.x, t = threadIdx.x;
    for (int i = t; i < 2112; i += 256) { sA[i] = 0.f; sB[i] = 0.f; uA[i] = 0.f; uB[i] = 0.f; }
    for (int i = t; i < 192; i += 256) {
        float fi = d_if[g * 192 + i], ui = d_iu[g * 192 + i];
        s_if[i] = fi; s_iu[i] = ui;
        s_mm[i] = fi; s_um[i] = ui;   // folded: mm_n + indiv_factor, um_n + indiv_util
    }
    for (int i = t; i < EPG; i += 256) s_fl[i] = d_flag[g * EPG + i];
    __syncthreads();

    for (int it = 0; it < NPG; ++it) {
        const float* om = (it & 1) ? sB : sA;
        const float* ou = (it & 1) ? uB : uA;
        float* nm = (it & 1) ? sA : sB;
        float* nu = (it & 1) ? uA : uB;
        for (int idx = t; idx < 2112; idx += 256) {
            int e = idx >> 4, a = idx & 15;
            unsigned mask = (t & 16) ? 0xFFFF0000u : 0x0000FFFFu;
            if (s_fl[e] == 0.f) continue;
            int s = e / 11;
            int rev = revloc(e);
            int ge = g * EPG + e;
            const float4* fvp = (const float4*)(d_fv + ge * 256 + a * 16);
            const float4* uvp = (const float4*)(d_uv + ge * 256 + a * 16);
            float4 f0 = fvp[0], f1 = fvp[1], f2 = fvp[2], f3 = fvp[3];
            float4 u0 = uvp[0], u1 = uvp[1], u2 = uvp[2], u3 = uvp[3];
            float fv[16] = {f0.x, f0.y, f0.z, f0.w, f1.x, f1.y, f1.z, f1.w,
                            f2.x, f2.y, f2.z, f2.w, f3.x, f3.y, f3.z, f3.w};
            float uv[16] = {u0.x, u0.y, u0.z, u0.w, u1.x, u1.y, u1.z, u1.w,
                            u2.x, u2.y, u2.z, u2.w, u3.x, u3.y, u3.z, u3.w};
            float m[16], mx = -1e30f;
#pragma unroll
            for (int b = 0; b < 16; ++b) {
                float agg = s_mm[s * 16 + b] - om[rev * 16 + b];
                m[b] = fv[b] + agg;
                mx = fmaxf(mx, m[b]);
            }
            float se = 0.f;
#pragma unroll
            for (int b = 0; b < 16; ++b) {
                float pb = __expf(m[b] - mx);
                m[b] = pb;            // reuse for softmax
                se += pb;
            }
            float lse = mx + __logf(se);
            float gm = lse;
#pragma unroll
            for (int w = 8; w > 0; w >>= 1) gm = fmaxf(gm, __shfl_xor_sync(mask, gm, w));
            float gs = __expf(lse - gm);
#pragma unroll
            for (int w = 8; w > 0; w >>= 1) gs += __shfl_xor_sync(mask, gs, w);
            float GL = gm + __logf(gs);
            nm[e * 16 + a] = lse - GL;
            float acc = 0.f;
#pragma unroll
            for (int b = 0; b < 16; ++b) {
                float util = s_um[s * 16 + b] - ou[rev * 16 + b];
                acc += (uv[b] + util) * m[b];
            }
            nu[e * 16 + a] = acc * __fdividef(1.f, se);
        }
        __syncthreads();
        if (t < 192) {
            int n = t >> 4, b = t & 15;
            float am = 0.f, au = 0.f;
#pragma unroll
            for (int s2 = 0; s2 < NPG; ++s2) {
                if (s2 == n) continue;
                int ee = s2 * 11 + n - (n > s2);
                am += nm[ee * 16 + b];
                au += nu[ee * 16 + b];
            }
            s_mm[t] = am + s_if[t];
            s_um[t] = au + s_iu[t];
        }
        __syncthreads();
    }
    if (t < 16) out[g * 16 + t] = s_um[t];   // um_n + indiv_util at node 0
}

extern "C" void kernel_launch(void* const* d_in, const int* in_sizes, int n_in,
                              void* d_out, int out_size) {
    const float* ef   = (const float*)d_in[0];
    const float* nf   = (const float*)d_in[1];
    const float* gf   = (const float*)d_in[2];
    const float* gn   = (const float*)d_in[7];
    const float* Wjf  = (const float*)d_in[8];
    const float* bjf  = (const float*)d_in[9];
    const float* Wif  = (const float*)d_in[10];
    const float* bif  = (const float*)d_in[11];
    const float* Wju  = (const float*)d_in[12];
    const float* bju  = (const float*)d_in[13];
    const float* Wiu  = (const float*)d_in[14];
    const float* biu  = (const float*)d_in[15];
    const float* Wfl  = (const float*)d_in[16];
    const float* bfl  = (const float*)d_in[17];
    const float* Wcls = (const float*)d_in[18];
    const float* bcls = (const float*)d_in[19];
    float* out = (float*)d_out;

    pack_w<<<(192 * NC + 255) / 256, 256>>>(Wjf, Wju, Wfl);
    gc_k<<<(B_ * NC + 255) / 256, 256>>>(gf, bjf, bju, bfl);
    node_k<<<NT, 32>>>(nf, gf, Wif, bif, Wiu, biu);
    flv_k<<<E_TOT / 128, 256>>>(ef, Wfl);
    flagc_k<<<E_TOT / 8, 256>>>(gn, Wcls, bcls);
    gemm_k<<<dim3(8, 132), 256>>>(ef);
    einsum_k<<<E_TOT / 4, 128>>>();
    bp_k<<<B_, 256>>>(out);
}

// round 5
// speedup vs baseline: 1.7418x; 1.1585x over previous
#include <cuda_runtime.h>

#define B_    128
#define NPG   12
#define EPG   132
#define E_TOT 16896
#define NT    1536
#define NC    1056   // 512 jf | 512 ju | 32 fl (in d_W / d_gc)

__device__ float d_W[192 * NC];
__device__ float d_gc[B_ * NC];
__device__ float d_fc[E_TOT * 1024];   // jf|ju rows, only flag-1 edges valid
__device__ float d_flv[E_TOT * 32];    // fl linear output
__device__ float d_fv[E_TOT * 256];
__device__ float d_uv[E_TOT * 256];
__device__ float d_flag[E_TOT];
__device__ float d_if[NT * 16];
__device__ float d_iu[NT * 16];
__device__ int   d_cnt;
__device__ int   d_list[E_TOT];

__device__ __forceinline__ unsigned long long pk2(float lo, float hi) {
    unsigned long long r;
    asm("mov.b64 %0, {%1, %2};" : "=l"(r) : "f"(lo), "f"(hi));
    return r;
}
__device__ __forceinline__ void fma2(unsigned long long& d, unsigned long long a, unsigned long long b) {
    asm("fma.rn.f32x2 %0, %1, %2, %0;" : "+l"(d) : "l"(a), "l"(b));
}
__device__ __forceinline__ void up2(unsigned long long v, float& lo, float& hi) {
    asm("mov.b64 {%0, %1}, %2;" : "=f"(lo), "=f"(hi) : "l"(v));
}
__device__ __forceinline__ int revloc(int ee) {
    int s = ee / 11, dd = ee - s * 11;
    int d = dd + (dd >= s);
    return d * 11 + s - (s > d);
}

// ---- K1: pack [W_jf|W_ju|W_fl] into d_W[k][j] ----
__global__ void pack_w(const float* __restrict__ Wjf, const float* __restrict__ Wju,
                       const float* __restrict__ Wfl) {
    int i = blockIdx.x * blockDim.x + threadIdx.x;
    if (i >= 192 * NC) return;
    int k = i / NC, j = i - k * NC;
    d_W[i] = (j < 512) ? Wjf[k * 512 + j]
           : (j < 1024) ? Wju[k * 512 + j - 512]
           : Wfl[k * 32 + j - 1024];
}

// ---- K2: per-graph part + bias ----
__global__ void gc_k(const float* __restrict__ gf, const float* __restrict__ bjf,
                     const float* __restrict__ bju, const float* __restrict__ bfl) {
    int i = blockIdx.x * blockDim.x + threadIdx.x;
    if (i >= B_ * NC) return;
    int g = i / NC, j = i - g * NC;
    float acc = (j < 512) ? bjf[j] : (j < 1024 ? bju[j - 512] : bfl[j - 1024]);
    const float* gr = gf + g * 64;
#pragma unroll 8
    for (int k = 0; k < 64; ++k) acc += gr[k] * d_W[(128 + k) * NC + j];
    d_gc[i] = acc;
}

// ---- K3: node linears ----
__global__ void node_k(const float* __restrict__ nf, const float* __restrict__ gf,
                       const float* __restrict__ Wif, const float* __restrict__ bif,
                       const float* __restrict__ Wiu, const float* __restrict__ biu) {
    __shared__ float xn[128];
    int n = blockIdx.x, t = threadIdx.x;
    int g = n / NPG;
    for (int i = t; i < 128; i += 32)
        xn[i] = (i < 64) ? nf[n * 64 + i] : gf[g * 64 + i - 64];
    __syncthreads();
    const float* W = (t < 16) ? Wif : Wiu;
    int col = t & 15;
    float acc = (t < 16) ? bif[col] : biu[col];
#pragma unroll 8
    for (int k = 0; k < 128; ++k) acc += xn[k] * W[k * 16 + col];
    if (t < 16) d_if[n * 16 + col] = acc;
    else        d_iu[n * 16 + col] = acc;
}

// ---- K4: fl linear for ALL edges (32 cols), occupancy-shaped ----
// 32 edges/block, 8 threads/edge, each thread owns 4 contiguous columns.
__global__ void __launch_bounds__(256) flv_k(const float* __restrict__ ef,
                                             const float* __restrict__ Wfl) {
    __shared__ __align__(16) float Ws[128 * 32];
    int t = threadIdx.x;
    for (int i = t * 4; i < 4096; i += 1024)
        *(float4*)&Ws[i] = *(const float4*)&Wfl[i];
    __syncthreads();
    int local = t >> 3;          // edge within block (0..31)
    int part  = t & 7;           // column group (0..7)
    int e = blockIdx.x * 32 + local;
    int g = e / EPG;
    int co = part * 4;
    float4 bias = *(const float4*)(d_gc + g * NC + 1024 + co);
    unsigned long long acc0 = pk2(bias.x, bias.y);
    unsigned long long acc1 = pk2(bias.z, bias.w);
    const float4* ep = (const float4*)(ef + e * 128);
#pragma unroll 8
    for (int k4 = 0; k4 < 32; ++k4) {
        float4 ev = ep[k4];
        float evs[4] = {ev.x, ev.y, ev.z, ev.w};
#pragma unroll
        for (int j = 0; j < 4; ++j) {
            int k = k4 * 4 + j;
            float4 w = *(const float4*)(Ws + k * 32 + co);
            unsigned long long aa = pk2(evs[j], evs[j]);
            fma2(acc0, aa, pk2(w.x, w.y));
            fma2(acc1, aa, pk2(w.z, w.w));
        }
    }
    float o0, o1, o2, o3;
    up2(acc0, o0, o1); up2(acc1, o2, o3);
    *(float4*)(d_flv + e * 32 + co) = make_float4(o0, o1, o2, o3);
    if (blockIdx.x == 0 && t == 0) d_cnt = 0;
}

// ---- K5: gumbel hard flag + compaction ----
__global__ void flagc_k(const float* __restrict__ noise, const float* __restrict__ Wc,
                        const float* __restrict__ bc) {
    int t = threadIdx.x, lane = t & 31;
    int e = blockIdx.x * 8 + (t >> 5);
    int g = e / EPG, ee = e - g * EPG;
    int r = g * EPG + revloc(ee);
    float p = d_flv[e * 32 + lane] * d_flv[r * 32 + lane];
    float l0 = p * Wc[lane * 2 + 0];
    float l1 = p * Wc[lane * 2 + 1];
#pragma unroll
    for (int m = 16; m > 0; m >>= 1) {
        l0 += __shfl_xor_sync(0xffffffffu, l0, m);
        l1 += __shfl_xor_sync(0xffffffffu, l1, m);
    }
    if (lane == 0) {
        int mn = min(e, r);
        float y0 = l0 + bc[0] + noise[2 * mn];
        float y1 = l1 + bc[1] + noise[2 * mn + 1];
        float f = (y0 >= y1) ? 1.f : 0.f;
        d_flag[e] = f;
        if (f != 0.f) {
            int s = atomicAdd(&d_cnt, 1);
            d_list[s] = e;
        }
    }
}

// ---- K6: gathered GEMM over flag-1 edges: d_fc[e] = ef[e] @ W[:,0:1024] + gc ----
__global__ void __launch_bounds__(256, 2) gemm_k(const float* __restrict__ ef) {
    __shared__ int sIdx[128];
    __shared__ __align__(16) float As[32][128];
    __shared__ __align__(16) float Bs[32][128];
    int cnt = d_cnt;
    int bm = blockIdx.y * 128;
    if (bm >= cnt) return;
    int bn = blockIdx.x * 128;
    int t = threadIdx.x;
    if (t < 128) sIdx[t] = d_list[min(bm + t, E_TOT - 1)];
    __syncthreads();
    int tx = t & 15, ty = t >> 4;
    unsigned long long c[8][4];
#pragma unroll
    for (int q = 0; q < 8; ++q)
#pragma unroll
        for (int j = 0; j < 4; ++j) c[q][j] = 0ULL;

    for (int kk = 0; kk < 128; kk += 32) {
#pragma unroll
        for (int i = 0; i < 4; ++i) {
            int idx = i * 256 + t;
            int m = idx & 127, k4 = idx >> 7;
            float4 v = *(const float4*)(ef + sIdx[m] * 128 + kk + k4 * 4);
            As[k4 * 4 + 0][m] = v.x; As[k4 * 4 + 1][m] = v.y;
            As[k4 * 4 + 2][m] = v.z; As[k4 * 4 + 3][m] = v.w;
        }
#pragma unroll
        for (int i = 0; i < 4; ++i) {
            int idx = i * 256 + t;
            int n4 = idx & 31, k = idx >> 5;
            *(float4*)&Bs[k][n4 * 4] = *(const float4*)(d_W + (kk + k) * NC + bn + n4 * 4);
        }
        __syncthreads();
#pragma unroll
        for (int k = 0; k < 32; ++k) {
            float4 b0 = *(const float4*)&Bs[k][tx * 8];
            float4 b1 = *(const float4*)&Bs[k][tx * 8 + 4];
            unsigned long long bb0 = pk2(b0.x, b0.y), bb1 = pk2(b0.z, b0.w);
            unsigned long long bb2 = pk2(b1.x, b1.y), bb3 = pk2(b1.z, b1.w);
            float4 a0 = *(const float4*)&As[k][ty * 8];
            float4 a1 = *(const float4*)&As[k][ty * 8 + 4];
            float av[8] = {a0.x, a0.y, a0.z, a0.w, a1.x, a1.y, a1.z, a1.w};
#pragma unroll
            for (int q = 0; q < 8; ++q) {
                unsigned long long aa = pk2(av[q], av[q]);
                fma2(c[q][0], aa, bb0); fma2(c[q][1], aa, bb1);
                fma2(c[q][2], aa, bb2); fma2(c[q][3], aa, bb3);
            }
        }
        __syncthreads();
    }
#pragma unroll
    for (int q = 0; q < 8; ++q) {
        int slot = bm + ty * 8 + q;
        if (slot < cnt) {
            int e = sIdx[ty * 8 + q];
            int g = e / EPG;
            int col = bn + tx * 8;
            float4 g0 = *(const float4*)(d_gc + g * NC + col);
            float4 g1 = *(const float4*)(d_gc + g * NC + col + 4);
            float o0, o1, o2, o3, o4, o5, o6, o7;
            up2(c[q][0], o0, o1); up2(c[q][1], o2, o3);
            up2(c[q][2], o4, o5); up2(c[q][3], o6, o7);
            float4 w0 = make_float4(o0 + g0.x, o1 + g0.y, o2 + g0.z, o3 + g0.w);
            float4 w1 = make_float4(o4 + g1.x, o5 + g1.y, o6 + g1.z, o7 + g1.w);
            *(float4*)(d_fc + e * 1024 + col) = w0;
            *(float4*)(d_fc + e * 1024 + col + 4) = w1;
        }
    }
}

// ---- K7: einsum over flag-1 edges ----
__global__ void einsum_k() {
    __shared__ __align__(16) float sE[4 * 1056];  // [le][mat*528 + a*33 + m]
    __shared__ __align__(16) float sR[4 * 1024];  // [le][mat*512 + m*16 + b]
    __shared__ int sID[4];
    int cnt = d_cnt;
    int base = blockIdx.x * 4;
    if (base >= cnt) return;
    int t = threadIdx.x;
    if (t < 4) sID[t] = d_list[min(base + t, E_TOT - 1)];
    __syncthreads();
#pragma unroll
    for (int i = 0; i < 16; ++i) {
        int idx = i * 128 + t;
        int side = idx >> 10, rem = idx & 1023;
        int le = rem >> 8, j = (rem & 255) * 4;
        int e = sID[le];
        int mat = j >> 9, w = j & 511, a2 = w >> 5, m = w & 31;
        if (side == 0) {
            float4 v = *(const float4*)(d_fc + e * 1024 + j);
            float* p = sE + le * 1056 + mat * 528 + a2 * 33 + m;
            p[0] = v.x; p[1] = v.y; p[2] = v.z; p[3] = v.w;
        } else {
            int g = e / EPG, ee = e - g * EPG;
            int r = g * EPG + revloc(ee);
            float4 v = *(const float4*)(d_fc + r * 1024 + j);
            float* p = sR + le * 1024 + mat * 512 + m * 16 + a2;
            p[0] = v.x; p[16] = v.y; p[32] = v.z; p[48] = v.w;
        }
    }
    __syncthreads();
    int le = t >> 5, lane = t & 31, a = lane & 15, half = lane >> 4;
    if (base + le >= cnt) return;
    int e = sID[le];
#pragma unroll
    for (int mat = 0; mat < 2; ++mat) {
        const float* Er = sE + le * 1056 + mat * 528 + a * 33;
        const float* Rr = sR + le * 1024 + mat * 512 + half * 8;
        unsigned long long acc[4];
#pragma unroll
        for (int j = 0; j < 4; ++j) acc[j] = 0ULL;
#pragma unroll
        for (int m = 0; m < 32; ++m) {
            float va = Er[m];
            unsigned long long aa = pk2(va, va);
            float4 r0 = *(const float4*)(Rr + m * 16);
            float4 r1 = *(const float4*)(Rr + m * 16 + 4);
            fma2(acc[0], aa, pk2(r0.x, r0.y)); fma2(acc[1], aa, pk2(r0.z, r0.w));
            fma2(acc[2], aa, pk2(r1.x, r1.y)); fma2(acc[3], aa, pk2(r1.z, r1.w));
        }
        float o0, o1, o2, o3, o4, o5, o6, o7;
        up2(acc[0], o0, o1); up2(acc[1], o2, o3);
        up2(acc[2], o4, o5); up2(acc[3], o6, o7);
        float* op = (mat ? d_uv : d_fv) + e * 256 + a * 16 + half * 8;
        *(float4*)op = make_float4(o0, o1, o2, o3);
        *(float4*)(op + 4) = make_float4(o4, o5, o6, o7);
    }
}

// ---- K8: BP, one CTA per graph, 512 threads, per-graph edge compaction ----
__global__ void __launch_bounds__(512) bp_k(float* __restrict__ out) {
    __shared__ float sA[2112], sB[2112], uA[2112], uB[2112];
    __shared__ float s_mm[192], s_um[192], s_if[192], s_iu[192];
    __shared__ int s_act[EPG];
    __shared__ int s_cnt;
    int g = blockIdx.x, t = threadIdx.x;
    if (t == 0) s_cnt = 0;
    for (int i = t; i < 2112; i += 512) { sA[i] = 0.f; sB[i] = 0.f; uA[i] = 0.f; uB[i] = 0.f; }
    if (t < 192) {
        float fi = d_if[g * 192 + t], ui = d_iu[g * 192 + t];
        s_if[t] = fi; s_iu[t] = ui;
        s_mm[t] = fi; s_um[t] = ui;   // folded: mm_n + indiv_factor
    }
    __syncthreads();
    if (t < EPG && d_flag[g * EPG + t] != 0.f) {
        int p = atomicAdd(&s_cnt, 1);
        s_act[p] = t;
    }
    __syncthreads();
    int cnt16 = s_cnt * 16;

    for (int it = 0; it < NPG; ++it) {
        const float* om = (it & 1) ? sB : sA;
        const float* ou = (it & 1) ? uB : uA;
        float* nm = (it & 1) ? sA : sB;
        float* nu = (it & 1) ? uA : uB;
        for (int idx = t; idx < cnt16; idx += 512) {
            int e = s_act[idx >> 4];
            int a = idx & 15;
            unsigned mask = (t & 16) ? 0xFFFF0000u : 0x0000FFFFu;
            int s = e / 11;
            int rev = revloc(e);
            int ge = g * EPG + e;
            const float4* fvp = (const float4*)(d_fv + ge * 256 + a * 16);
            const float4* uvp = (const float4*)(d_uv + ge * 256 + a * 16);
            float4 f0 = fvp[0], f1 = fvp[1], f2 = fvp[2], f3 = fvp[3];
            float4 u0 = uvp[0], u1 = uvp[1], u2 = uvp[2], u3 = uvp[3];
            float fv[16] = {f0.x, f0.y, f0.z, f0.w, f1.x, f1.y, f1.z, f1.w,
                            f2.x, f2.y, f2.z, f2.w, f3.x, f3.y, f3.z, f3.w};
            float uv[16] = {u0.x, u0.y, u0.z, u0.w, u1.x, u1.y, u1.z, u1.w,
                            u2.x, u2.y, u2.z, u2.w, u3.x, u3.y, u3.z, u3.w};
            float m[16], mx = -1e30f;
#pragma unroll
            for (int b = 0; b < 16; ++b) {
                float agg = s_mm[s * 16 + b] - om[rev * 16 + b];
                m[b] = fv[b] + agg;
                mx = fmaxf(mx, m[b]);
            }
            float se = 0.f;
#pragma unroll
            for (int b = 0; b < 16; ++b) {
                float pb = __expf(m[b] - mx);
                m[b] = pb;
                se += pb;
            }
            float lse = mx + __logf(se);
            float gm = lse;
#pragma unroll
            for (int w = 8; w > 0; w >>= 1) gm = fmaxf(gm, __shfl_xor_sync(mask, gm, w));
            float gs = __expf(lse - gm);
#pragma unroll
            for (int w = 8; w > 0; w >>= 1) gs += __shfl_xor_sync(mask, gs, w);
            float GL = gm + __logf(gs);
            nm[e * 16 + a] = lse - GL;
            float acc = 0.f;
#pragma unroll
            for (int b = 0; b < 16; ++b) {
                float util = s_um[s * 16 + b] - ou[rev * 16 + b];
                acc += (uv[b] + util) * m[b];
            }
            nu[e * 16 + a] = acc * __fdividef(1.f, se);
        }
        __syncthreads();
        if (t < 192) {
            int n = t >> 4, b = t & 15;
            float am = 0.f, au = 0.f;
#pragma unroll
            for (int s2 = 0; s2 < NPG; ++s2) {
                if (s2 == n) continue;
                int ee = s2 * 11 + n - (n > s2);
                am += nm[ee * 16 + b];
                au += nu[ee * 16 + b];
            }
            s_mm[t] = am + s_if[t];
            s_um[t] = au + s_iu[t];
        }
        __syncthreads();
    }
    if (t < 16) out[g * 16 + t] = s_um[t];
}

extern "C" void kernel_launch(void* const* d_in, const int* in_sizes, int n_in,
                              void* d_out, int out_size) {
    const float* ef   = (const float*)d_in[0];
    const float* nf   = (const float*)d_in[1];
    const float* gf   = (const float*)d_in[2];
    const float* gn   = (const float*)d_in[7];
    const float* Wjf  = (const float*)d_in[8];
    const float* bjf  = (const float*)d_in[9];
    const float* Wif  = (const float*)d_in[10];
    const float* bif  = (const float*)d_in[11];
    const float* Wju  = (const float*)d_in[12];
    const float* bju  = (const float*)d_in[13];
    const float* Wiu  = (const float*)d_in[14];
    const float* biu  = (const float*)d_in[15];
    const float* Wfl  = (const float*)d_in[16];
    const float* bfl  = (const float*)d_in[17];
    const float* Wcls = (const float*)d_in[18];
    const float* bcls = (const float*)d_in[19];
    float* out = (float*)d_out;

    pack_w<<<(192 * NC + 255) / 256, 256>>>(Wjf, Wju, Wfl);
    gc_k<<<(B_ * NC + 255) / 256, 256>>>(gf, bjf, bju, bfl);
    node_k<<<NT, 32>>>(nf, gf, Wif, bif, Wiu, biu);
    flv_k<<<E_TOT / 32, 256>>>(ef, Wfl);
    flagc_k<<<E_TOT / 8, 256>>>(gn, Wcls, bcls);
    gemm_k<<<dim3(8, 132), 256>>>(ef);
    einsum_k<<<E_TOT / 4, 128>>>();
    bp_k<<<B_, 512>>>(out);
}

// round 7
// speedup vs baseline: 1.7998x; 1.0333x over previous
#include <cuda_runtime.h>

#define B_    128
#define NPG   12
#define EPG   132
#define E_TOT 16896
#define NT    1536
#define NC    1056   // 512 jf | 512 ju | 32 fl (in d_W / d_gc)

__device__ float d_W[128 * NC];        // only the edge-feature rows (k<128)
__device__ float d_gc[B_ * NC];
__device__ float d_fc[E_TOT * 1024];   // jf|ju rows, only flag-1 edges valid
__device__ float d_flv[E_TOT * 32];    // fl linear output
__device__ float d_fv[E_TOT * 256];
__device__ float d_uv[E_TOT * 256];
__device__ float d_flag[E_TOT];
__device__ float d_if[NT * 16];
__device__ float d_iu[NT * 16];
__device__ int   d_cnt;
__device__ int   d_list[E_TOT];

__device__ __forceinline__ unsigned long long pk2(float lo, float hi) {
    unsigned long long r;
    asm("mov.b64 %0, {%1, %2};" : "=l"(r) : "f"(lo), "f"(hi));
    return r;
}
__device__ __forceinline__ void fma2(unsigned long long& d, unsigned long long a, unsigned long long b) {
    asm("fma.rn.f32x2 %0, %1, %2, %0;" : "+l"(d) : "l"(a), "l"(b));
}
__device__ __forceinline__ void up2(unsigned long long v, float& lo, float& hi) {
    asm("mov.b64 {%0, %1}, %2;" : "=f"(lo), "=f"(hi) : "l"(v));
}
__device__ __forceinline__ int revloc(int ee) {
    int s = ee / 11, dd = ee - s * 11;
    int d = dd + (dd >= s);
    return d * 11 + s - (s > d);
}

// ---- K1: pack [W_jf|W_ju|W_fl] rows 0..127 into d_W[k][j] ----
__global__ void pack_w(const float* __restrict__ Wjf, const float* __restrict__ Wju,
                       const float* __restrict__ Wfl) {
    int i = blockIdx.x * blockDim.x + threadIdx.x;
    if (i >= 128 * NC) return;
    int k = i / NC, j = i - k * NC;
    d_W[i] = (j < 512) ? Wjf[k * 512 + j]
           : (j < 1024) ? Wju[k * 512 + j - 512]
           : Wfl[k * 32 + j - 1024];
}

// ---- K2: per-graph part + bias (reads raw weights, rows 128..191) ----
__global__ void gc_k(const float* __restrict__ gf,
                     const float* __restrict__ Wjf, const float* __restrict__ bjf,
                     const float* __restrict__ Wju, const float* __restrict__ bju,
                     const float* __restrict__ Wfl, const float* __restrict__ bfl) {
    int i = blockIdx.x * blockDim.x + threadIdx.x;
    if (i >= B_ * NC) return;
    int g = i / NC, j = i - g * NC;
    const float* Wp; int st; float acc;
    if (j < 512)        { Wp = Wjf + 128 * 512 + j;          st = 512; acc = bjf[j]; }
    else if (j < 1024)  { Wp = Wju + 128 * 512 + (j - 512);  st = 512; acc = bju[j - 512]; }
    else                { Wp = Wfl + 128 * 32  + (j - 1024); st = 32;  acc = bfl[j - 1024]; }
    const float* gr = gf + g * 64;
#pragma unroll 8
    for (int k = 0; k < 64; ++k) acc += gr[k] * Wp[k * st];
    d_gc[i] = acc;
}

// ---- K3: node linears, 8 nodes per 256-thread block ----
__global__ void __launch_bounds__(256) node_k(
        const float* __restrict__ nf, const float* __restrict__ gf,
        const float* __restrict__ Wif, const float* __restrict__ bif,
        const float* __restrict__ Wiu, const float* __restrict__ biu) {
    __shared__ float xn[8][128];
    int t = threadIdx.x;
    int nb = blockIdx.x * 8;
    for (int i = t; i < 1024; i += 256) {
        int node = i >> 7, kk = i & 127;
        xn[node][kk] = (kk < 64) ? nf[(nb + node) * 64 + kk]
                                 : gf[((nb + node) / NPG) * 64 + kk - 64];
    }
    __syncthreads();
    int w = t >> 5, lane = t & 31;
    int n = nb + w;
    const float* W = (lane < 16) ? Wif : Wiu;
    int col = lane & 15;
    float acc = (lane < 16) ? bif[col] : biu[col];
#pragma unroll 8
    for (int k = 0; k < 128; ++k) acc += xn[w][k] * W[k * 16 + col];
    if (lane < 16) d_if[n * 16 + col] = acc;
    else           d_iu[n * 16 + col] = acc;
}

// ---- K4: fl linear, tiled GEMM: 128 edges x 32 cols per CTA, BK=32 ----
__global__ void __launch_bounds__(256) flv_k(const float* __restrict__ ef,
                                             const float* __restrict__ Wfl) {
    __shared__ __align__(16) float As[32][128];
    __shared__ __align__(16) float Bs[32][32];
    int bm = blockIdx.x * 128;
    int t = threadIdx.x;
    int tx = t & 7, ty = t >> 3;
    unsigned long long acc[4][2];
#pragma unroll
    for (int q = 0; q < 4; ++q) { acc[q][0] = 0ULL; acc[q][1] = 0ULL; }

    for (int kk = 0; kk < 128; kk += 32) {
#pragma unroll
        for (int i = 0; i < 4; ++i) {
            int idx = i * 256 + t;
            int m = idx & 127, k4 = idx >> 7;
            float4 v = *(const float4*)(ef + (bm + m) * 128 + kk + k4 * 4);
            As[k4 * 4 + 0][m] = v.x; As[k4 * 4 + 1][m] = v.y;
            As[k4 * 4 + 2][m] = v.z; As[k4 * 4 + 3][m] = v.w;
        }
        {
            int k = t >> 3, c4 = t & 7;
            *(float4*)&Bs[k][c4 * 4] = *(const float4*)(Wfl + (kk + k) * 32 + c4 * 4);
        }
        __syncthreads();
#pragma unroll
        for (int k = 0; k < 32; ++k) {
            float4 b = *(const float4*)&Bs[k][tx * 4];
            unsigned long long bb0 = pk2(b.x, b.y), bb1 = pk2(b.z, b.w);
            float4 a = *(const float4*)&As[k][ty * 4];
            float av[4] = {a.x, a.y, a.z, a.w};
#pragma unroll
            for (int q = 0; q < 4; ++q) {
                unsigned long long aa = pk2(av[q], av[q]);
                fma2(acc[q][0], aa, bb0);
                fma2(acc[q][1], aa, bb1);
            }
        }
        __syncthreads();
    }
#pragma unroll
    for (int q = 0; q < 4; ++q) {
        int e = bm + ty * 4 + q;
        int g = e / EPG;
        float4 bias = *(const float4*)(d_gc + g * NC + 1024 + tx * 4);
        float o0, o1, o2, o3;
        up2(acc[q][0], o0, o1); up2(acc[q][1], o2, o3);
        *(float4*)(d_flv + e * 32 + tx * 4) =
            make_float4(o0 + bias.x, o1 + bias.y, o2 + bias.z, o3 + bias.w);
    }
    if (blockIdx.x == 0 && t == 0) d_cnt = 0;
}

// ---- K5: gumbel hard flag + compaction ----
__global__ void flagc_k(const float* __restrict__ noise, const float* __restrict__ Wc,
                        const float* __restrict__ bc) {
    int t = threadIdx.x, lane = t & 31;
    int e = blockIdx.x * 8 + (t >> 5);
    int g = e / EPG, ee = e - g * EPG;
    int r = g * EPG + revloc(ee);
    float p = d_flv[e * 32 + lane] * d_flv[r * 32 + lane];
    float l0 = p * Wc[lane * 2 + 0];
    float l1 = p * Wc[lane * 2 + 1];
#pragma unroll
    for (int m = 16; m > 0; m >>= 1) {
        l0 += __shfl_xor_sync(0xffffffffu, l0, m);
        l1 += __shfl_xor_sync(0xffffffffu, l1, m);
    }
    if (lane == 0) {
        int mn = min(e, r);
        float y0 = l0 + bc[0] + noise[2 * mn];
        float y1 = l1 + bc[1] + noise[2 * mn + 1];
        float f = (y0 >= y1) ? 1.f : 0.f;
        d_flag[e] = f;
        if (f != 0.f) {
            int s = atomicAdd(&d_cnt, 1);
            d_list[s] = e;
        }
    }
}

// ---- K6: gathered GEMM over flag-1 edges: d_fc[e] = ef[e] @ W[:,0:1024] + gc ----
__global__ void __launch_bounds__(256, 2) gemm_k(const float* __restrict__ ef) {
    __shared__ int sIdx[128];
    __shared__ __align__(16) float As[32][128];
    __shared__ __align__(16) float Bs[32][128];
    int cnt = d_cnt;
    int bm = blockIdx.y * 128;
    if (bm >= cnt) return;
    int bn = blockIdx.x * 128;
    int t = threadIdx.x;
    if (t < 128) sIdx[t] = d_list[min(bm + t, E_TOT - 1)];
    __syncthreads();
    int tx = t & 15, ty = t >> 4;
    unsigned long long c[8][4];
#pragma unroll
    for (int q = 0; q < 8; ++q)
#pragma unroll
        for (int j = 0; j < 4; ++j) c[q][j] = 0ULL;

    for (int kk = 0; kk < 128; kk += 32) {
#pragma unroll
        for (int i = 0; i < 4; ++i) {
            int idx = i * 256 + t;
            int m = idx & 127, k4 = idx >> 7;
            float4 v = *(const float4*)(ef + sIdx[m] * 128 + kk + k4 * 4);
            As[k4 * 4 + 0][m] = v.x; As[k4 * 4 + 1][m] = v.y;
            As[k4 * 4 + 2][m] = v.z; As[k4 * 4 + 3][m] = v.w;
        }
#pragma unroll
        for (int i = 0; i < 4; ++i) {
            int idx = i * 256 + t;
            int n4 = idx & 31, k = idx >> 5;
            *(float4*)&Bs[k][n4 * 4] = *(const float4*)(d_W + (kk + k) * NC + bn + n4 * 4);
        }
        __syncthreads();
#pragma unroll
        for (int k = 0; k < 32; ++k) {
            float4 b0 = *(const float4*)&Bs[k][tx * 8];
            float4 b1 = *(const float4*)&Bs[k][tx * 8 + 4];
            unsigned long long bb0 = pk2(b0.x, b0.y), bb1 = pk2(b0.z, b0.w);
            unsigned long long bb2 = pk2(b1.x, b1.y), bb3 = pk2(b1.z, b1.w);
            float4 a0 = *(const float4*)&As[k][ty * 8];
            float4 a1 = *(const float4*)&As[k][ty * 8 + 4];
            float av[8] = {a0.x, a0.y, a0.z, a0.w, a1.x, a1.y, a1.z, a1.w};
#pragma unroll
            for (int q = 0; q < 8; ++q) {
                unsigned long long aa = pk2(av[q], av[q]);
                fma2(c[q][0], aa, bb0); fma2(c[q][1], aa, bb1);
                fma2(c[q][2], aa, bb2); fma2(c[q][3], aa, bb3);
            }
        }
        __syncthreads();
    }
#pragma unroll
    for (int q = 0; q < 8; ++q) {
        int slot = bm + ty * 8 + q;
        if (slot < cnt) {
            int e = sIdx[ty * 8 + q];
            int g = e / EPG;
            int col = bn + tx * 8;
            float4 g0 = *(const float4*)(d_gc + g * NC + col);
            float4 g1 = *(const float4*)(d_gc + g * NC + col + 4);
            float o0, o1, o2, o3, o4, o5, o6, o7;
            up2(c[q][0], o0, o1); up2(c[q][1], o2, o3);
            up2(c[q][2], o4, o5); up2(c[q][3], o6, o7);
            float4 w0 = make_float4(o0 + g0.x, o1 + g0.y, o2 + g0.z, o3 + g0.w);
            float4 w1 = make_float4(o4 + g1.x, o5 + g1.y, o6 + g1.z, o7 + g1.w);
            *(float4*)(d_fc + e * 1024 + col) = w0;
            *(float4*)(d_fc + e * 1024 + col + 4) = w1;
        }
    }
}

// ---- K7: einsum over flag-1 edges ----
__global__ void einsum_k() {
    __shared__ __align__(16) float sE[4 * 1056];
    __shared__ __align__(16) float sR[4 * 1024];
    __shared__ int sID[4];
    int cnt = d_cnt;
    int base = blockIdx.x * 4;
    if (base >= cnt) return;
    int t = threadIdx.x;
    if (t < 4) sID[t] = d_list[min(base + t, E_TOT - 1)];
    __syncthreads();
#pragma unroll
    for (int i = 0; i < 16; ++i) {
        int idx = i * 128 + t;
        int side = idx >> 10, rem = idx & 1023;
        int le = rem >> 8, j = (rem & 255) * 4;
        int e = sID[le];
        int mat = j >> 9, w = j & 511, a2 = w >> 5, m = w & 31;
        if (side == 0) {
            float4 v = *(const float4*)(d_fc + e * 1024 + j);
            float* p = sE + le * 1056 + mat * 528 + a2 * 33 + m;
            p[0] = v.x; p[1] = v.y; p[2] = v.z; p[3] = v.w;
        } else {
            int g = e / EPG, ee = e - g * EPG;
            int r = g * EPG + revloc(ee);
            float4 v = *(const float4*)(d_fc + r * 1024 + j);
            float* p = sR + le * 1024 + mat * 512 + m * 16 + a2;
            p[0] = v.x; p[16] = v.y; p[32] = v.z; p[48] = v.w;
        }
    }
    __syncthreads();
    int le = t >> 5, lane = t & 31, a = lane & 15, half = lane >> 4;
    if (base + le >= cnt) return;
    int e = sID[le];
#pragma unroll
    for (int mat = 0; mat < 2; ++mat) {
        const float* Er = sE + le * 1056 + mat * 528 + a * 33;
        const float* Rr = sR + le * 1024 + mat * 512 + half * 8;
        unsigned long long acc[4];
#pragma unroll
        for (int j = 0; j < 4; ++j) acc[j] = 0ULL;
#pragma unroll
        for (int m = 0; m < 32; ++m) {
            float va = Er[m];
            unsigned long long aa = pk2(va, va);
            float4 r0 = *(const float4*)(Rr + m * 16);
            float4 r1 = *(const float4*)(Rr + m * 16 + 4);
            fma2(acc[0], aa, pk2(r0.x, r0.y)); fma2(acc[1], aa, pk2(r0.z, r0.w));
            fma2(acc[2], aa, pk2(r1.x, r1.y)); fma2(acc[3], aa, pk2(r1.z, r1.w));
        }
        float o0, o1, o2, o3, o4, o5, o6, o7;
        up2(acc[0], o0, o1); up2(acc[1], o2, o3);
        up2(acc[2], o4, o5); up2(acc[3], o6, o7);
        float* op = (mat ? d_uv : d_fv) + e * 256 + a * 16 + half * 8;
        *(float4*)op = make_float4(o0, o1, o2, o3);
        *(float4*)(op + 4) = make_float4(o4, o5, o6, o7);
    }
}

// ---- K8: BP, one CTA per graph, 512 threads, fv cached in dynamic smem ----
__global__ void __launch_bounds__(512) bp_k(float* __restrict__ out) {
    extern __shared__ __align__(16) float sm[];
    float* s_fv = sm;                      // 132*256
    float* sA   = sm + 33792;              // 2112
    float* sB   = sA + 2112;
    float* uA   = sB + 2112;
    float* uB   = uA + 2112;
    float* s_mm = uB + 2112;               // 192
    float* s_um = s_mm + 192;
    float* s_if = s_um + 192;
    float* s_iu = s_if + 192;
    int*   s_act = (int*)(s_iu + 192);     // 132
    int*   s_cntp = s_act + 132;

    int g = blockIdx.x, t = threadIdx.x;
    if (t == 0) *s_cntp = 0;
    for (int i = t; i < 2112; i += 512) { sA[i] = 0.f; sB[i] = 0.f; uA[i] = 0.f; uB[i] = 0.f; }
    if (t < 192) {
        float fi = d_if[g * 192 + t], ui = d_iu[g * 192 + t];
        s_if[t] = fi; s_iu[t] = ui;
        s_mm[t] = fi; s_um[t] = ui;
    }
    __syncthreads();
    if (t < EPG && d_flag[g * EPG + t] != 0.f) {
        int p = atomicAdd(s_cntp, 1);
        s_act[p] = t;
    }
    __syncthreads();
    int cnt = *s_cntp;
    int cnt16 = cnt * 16;
    // gather fv into smem with XOR chunk swizzle: chunk' = a*4 + (q ^ (a>>2))
    for (int i = t; i < cnt * 64; i += 512) {
        int p = i >> 6, c = i & 63;
        int a = c >> 2, q = c & 3;
        int e = s_act[p];
        float4 v = *(const float4*)(d_fv + (g * EPG + e) * 256 + c * 4);
        int sw = a * 4 + (q ^ (a >> 2));
        *(float4*)(s_fv + p * 256 + sw * 4) = v;
    }
    __syncthreads();

    for (int it = 0; it < NPG; ++it) {
        const float* om = (it & 1) ? sB : sA;
        const float* ou = (it & 1) ? uB : uA;
        float* nm = (it & 1) ? sA : sB;
        float* nu = (it & 1) ? uA : uB;
        for (int idx = t; idx < cnt16; idx += 512) {
            int p = idx >> 4;
            int e = s_act[p];
            int a = idx & 15;
            unsigned mask = (t & 16) ? 0xFFFF0000u : 0x0000FFFFu;
            int s = e / 11;
            int rev = revloc(e);
            int ge = g * EPG + e;
            const float* fvb = s_fv + p * 256;
            int ax4 = a * 4, ash = a >> 2;
            float4 f0 = *(const float4*)(fvb + (ax4 + (0 ^ ash)) * 4);
            float4 f1 = *(const float4*)(fvb + (ax4 + (1 ^ ash)) * 4);
            float4 f2 = *(const float4*)(fvb + (ax4 + (2 ^ ash)) * 4);
            float4 f3 = *(const float4*)(fvb + (ax4 + (3 ^ ash)) * 4);
            const float4* uvp = (const float4*)(d_uv + ge * 256 + a * 16);
            float4 u0 = uvp[0], u1 = uvp[1], u2 = uvp[2], u3 = uvp[3];
            float fv[16] = {f0.x, f0.y, f0.z, f0.w, f1.x, f1.y, f1.z, f1.w,
                            f2.x, f2.y, f2.z, f2.w, f3.x, f3.y, f3.z, f3.w};
            float uv[16] = {u0.x, u0.y, u0.z, u0.w, u1.x, u1.y, u1.z, u1.w,
                            u2.x, u2.y, u2.z, u2.w, u3.x, u3.y, u3.z, u3.w};
            float m[16], mx = -1e30f;
#pragma unroll
            for (int b = 0; b < 16; ++b) {
                float agg = s_mm[s * 16 + b] - om[rev * 16 + b];
                m[b] = fv[b] + agg;
                mx = fmaxf(mx, m[b]);
            }
            float se = 0.f;
#pragma unroll
            for (int b = 0; b < 16; ++b) {
                float pb = __expf(m[b] - mx);
                m[b] = pb;
                se += pb;
            }
            float lse = mx + __logf(se);
            float gm = lse;
#pragma unroll
            for (int w = 8; w > 0; w >>= 1) gm = fmaxf(gm, __shfl_xor_sync(mask, gm, w));
            float gs = __expf(lse - gm);
#pragma unroll
            for (int w = 8; w > 0; w >>= 1) gs += __shfl_xor_sync(mask, gs, w);
            float GL = gm + __logf(gs);
            nm[e * 16 + a] = lse - GL;
            float acc = 0.f;
#pragma unroll
            for (int b = 0; b < 16; ++b) {
                float util = s_um[s * 16 + b] - ou[rev * 16 + b];
                acc += (uv[b] + util) * m[b];
            }
            nu[e * 16 + a] = acc * __fdividef(1.f, se);
        }
        __syncthreads();
        if (t < 192) {
            int n = t >> 4, b = t & 15;
            float am = 0.f, au = 0.f;
#pragma unroll
            for (int s2 = 0; s2 < NPG; ++s2) {
                if (s2 == n) continue;
                int ee = s2 * 11 + n - (n > s2);
                am += nm[ee * 16 + b];
                au += nu[ee * 16 + b];
            }
            s_mm[t] = am + s_if[t];
            s_um[t] = au + s_iu[t];
        }
        __syncthreads();
    }
    if (t < 16) out[g * 16 + t] = s_um[t];
}

#define BP_SMEM ((33792 + 4 * 2112 + 4 * 192) * 4 + 136 * 4)

extern "C" void kernel_launch(void* const* d_in, const int* in_sizes, int n_in,
                              void* d_out, int out_size) {
    const float* ef   = (const float*)d_in[0];
    const float* nf   = (const float*)d_in[1];
    const float* gf   = (const float*)d_in[2];
    const float* gn   = (const float*)d_in[7];
    const float* Wjf  = (const float*)d_in[8];
    const float* bjf  = (const float*)d_in[9];
    const float* Wif  = (const float*)d_in[10];
    const float* bif  = (const float*)d_in[11];
    const float* Wju  = (const float*)d_in[12];
    const float* bju  = (const float*)d_in[13];
    const float* Wiu  = (const float*)d_in[14];
    const float* biu  = (const float*)d_in[15];
    const float* Wfl  = (const float*)d_in[16];
    const float* bfl  = (const float*)d_in[17];
    const float* Wcls = (const float*)d_in[18];
    const float* bcls = (const float*)d_in[19];
    float* out = (float*)d_out;

    static int smem_set = 0;
    if (!smem_set) {
        cudaFuncSetAttribute(bp_k, cudaFuncAttributeMaxDynamicSharedMemorySize, BP_SMEM);
        smem_set = 1;
    }

    pack_w<<<(128 * NC + 255) / 256, 256>>>(Wjf, Wju, Wfl);
    gc_k<<<(B_ * NC + 255) / 256, 256>>>(gf, Wjf, bjf, Wju, bju, Wfl, bfl);
    node_k<<<NT / 8, 256>>>(nf, gf, Wif, bif, Wiu, biu);
    flv_k<<<E_TOT / 128, 256>>>(ef, Wfl);
    flagc_k<<<E_TOT / 8, 256>>>(gn, Wcls, bcls);
    gemm_k<<<dim3(8, 132), 256>>>(ef);
    einsum_k<<<E_TOT / 4, 128>>>();
    bp_k<<<B_, 512, BP_SMEM>>>(out);
}

// round 8
// speedup vs baseline: 2.1859x; 1.2146x over previous
#include <cuda_runtime.h>
#include <cstdint>

#define B_    128
#define NPG   12
#define EPG   132
#define E_TOT 16896
#define NT    1536
#define NC    1056   // 512 jf | 512 ju | 32 fl (in d_gc)

__device__ float d_Wt[131072];         // tf32-prerounded, fragment-swizzled [nt][ks][wn][lane][f][r]
__device__ float d_gc[B_ * NC];
__device__ float d_fc[E_TOT * 1024];   // jf|ju rows, only flag-1 edges valid
__device__ float d_fv[E_TOT * 256];
__device__ float d_uv[E_TOT * 256];
__device__ float d_flag[E_TOT];
__device__ float d_if[NT * 16];
__device__ float d_iu[NT * 16];
__device__ int   d_cnt;
__device__ int   d_list[E_TOT];

__device__ __forceinline__ unsigned long long pk2(float lo, float hi) {
    unsigned long long r;
    asm("mov.b64 %0, {%1, %2};" : "=l"(r) : "f"(lo), "f"(hi));
    return r;
}
__device__ __forceinline__ void fma2(unsigned long long& d, unsigned long long a, unsigned long long b) {
    asm("fma.rn.f32x2 %0, %1, %2, %0;" : "+l"(d) : "l"(a), "l"(b));
}
__device__ __forceinline__ void up2(unsigned long long v, float& lo, float& hi) {
    asm("mov.b64 {%0, %1}, %2;" : "=f"(lo), "=f"(hi) : "l"(v));
}
__device__ __forceinline__ int revloc(int ee) {
    int s = ee / 11, dd = ee - s * 11;
    int d = dd + (dd >= s);
    return d * 11 + s - (s > d);
}
__device__ __forceinline__ void mma_tf32(float* d, const uint32_t* a, uint32_t b0, uint32_t b1) {
    asm volatile("mma.sync.aligned.m16n8k8.row.col.f32.tf32.tf32.f32 "
        "{%0,%1,%2,%3}, {%4,%5,%6,%7}, {%8,%9}, {%0,%1,%2,%3};\n"
        : "+f"(d[0]), "+f"(d[1]), "+f"(d[2]), "+f"(d[3])
        : "r"(a[0]), "r"(a[1]), "r"(a[2]), "r"(a[3]), "r"(b0), "r"(b1));
}
__device__ __forceinline__ uint32_t to_tf32(float v) {
    uint32_t r;
    asm("cvt.rna.tf32.f32 %0, %1;" : "=r"(r) : "f"(v));
    return r;
}

// ---- K1: fused prep: Wt pack (blocks 0..511) | gc (512..1039) | node lin (1040..1231) ----
__global__ void __launch_bounds__(256) prep_k(
        const float* __restrict__ Wjf, const float* __restrict__ bjf,
        const float* __restrict__ Wju, const float* __restrict__ bju,
        const float* __restrict__ Wfl, const float* __restrict__ bfl,
        const float* __restrict__ gf,  const float* __restrict__ nf,
        const float* __restrict__ Wif, const float* __restrict__ bif,
        const float* __restrict__ Wiu, const float* __restrict__ biu) {
    __shared__ float xn[8][128];
    int b = blockIdx.x, t = threadIdx.x;
    if (b == 0 && t == 0) d_cnt = 0;
    if (b < 512) {
        int i = b * 256 + t;
        int r = i & 1, f = (i >> 1) & 7, lane = (i >> 4) & 31;
        int wn = (i >> 9) & 1, ks = (i >> 10) & 15, nt = (i >> 14) & 7;
        int j = nt * 128 + wn * 64 + f * 8 + (lane >> 2);
        int k = ks * 8 + (lane & 3) + r * 4;
        float v = (j < 512) ? Wjf[k * 512 + j] : Wju[k * 512 + j - 512];
        d_Wt[i] = __uint_as_float(to_tf32(v));
    } else if (b < 1040) {
        int i = (b - 512) * 256 + t;      // < 135168
        int g = i / NC, j = i - g * NC;
        const float* Wp; int st; float acc;
        if (j < 512)        { Wp = Wjf + 128 * 512 + j;          st = 512; acc = bjf[j]; }
        else if (j < 1024)  { Wp = Wju + 128 * 512 + (j - 512);  st = 512; acc = bju[j - 512]; }
        else                { Wp = Wfl + 128 * 32  + (j - 1024); st = 32;  acc = bfl[j - 1024]; }
        const float* gr = gf + g * 64;
#pragma unroll 8
        for (int k = 0; k < 64; ++k) acc += gr[k] * Wp[k * st];
        d_gc[i] = acc;
    } else {
        int nb = (b - 1040) * 8;
        for (int i = t; i < 1024; i += 256) {
            int node = i >> 7, kk = i & 127;
            xn[node][kk] = (kk < 64) ? nf[(nb + node) * 64 + kk]
                                     : gf[((nb + node) / NPG) * 64 + kk - 64];
        }
        __syncthreads();
        int w = t >> 5, lane = t & 31;
        int n = nb + w;
        const float* W = (lane < 16) ? Wif : Wiu;
        int col = lane & 15;
        float acc = (lane < 16) ? bif[col] : biu[col];
#pragma unroll 8
        for (int k = 0; k < 128; ++k) acc += xn[w][k] * W[k * 16 + col];
        if (lane < 16) d_if[n * 16 + col] = acc;
        else           d_iu[n * 16 + col] = acc;
    }
}

// ---- K2: fused fl-linear + gumbel flag + compaction, one CTA per graph ----
#define FLV_THREADS 264
#define FLV_SMEM ((132 * 132 + 128 * 32 + 132 * 32 + 64) * 4)
__global__ void __launch_bounds__(FLV_THREADS) flvflag_k(
        const float* __restrict__ ef, const float* __restrict__ Wfl,
        const float* __restrict__ noise, const float* __restrict__ Wc,
        const float* __restrict__ bc) {
    extern __shared__ __align__(16) float fsm[];
    float* s_ef = fsm;                      // 132 rows x 132 (128 used)
    float* s_W  = fsm + 132 * 132;          // 128 x 32
    float* s_fl = s_W + 128 * 32;           // 132 x 32
    float* s_Wc = s_fl + 132 * 32;          // 64
    int g = blockIdx.x, t = threadIdx.x;
    for (int i = t; i < 4224; i += FLV_THREADS) {
        int r = i >> 5, q = i & 31;
        float4 v = *(const float4*)(ef + (g * EPG + r) * 128 + q * 4);
        *(float4*)(s_ef + r * 132 + q * 4) = v;
    }
    for (int i = t; i < 1024; i += FLV_THREADS)
        *(float4*)(s_W + i * 4) = *(const float4*)(Wfl + i * 4);
    if (t < 64) s_Wc[t] = Wc[t];
    __syncthreads();
    {
        int e = t >> 1, co = (t & 1) * 16;
        unsigned long long acc[8];
        const float* gb = d_gc + g * NC + 1024 + co;
#pragma unroll
        for (int c = 0; c < 8; ++c) acc[c] = pk2(gb[c * 2], gb[c * 2 + 1]);
        const float* er = s_ef + e * 132;
#pragma unroll 4
        for (int k = 0; k < 128; ++k) {
            float a = er[k];
            unsigned long long aa = pk2(a, a);
            const float4* wr = (const float4*)(s_W + k * 32 + co);
            float4 w0 = wr[0], w1 = wr[1], w2 = wr[2], w3 = wr[3];
            fma2(acc[0], aa, pk2(w0.x, w0.y)); fma2(acc[1], aa, pk2(w0.z, w0.w));
            fma2(acc[2], aa, pk2(w1.x, w1.y)); fma2(acc[3], aa, pk2(w1.z, w1.w));
            fma2(acc[4], aa, pk2(w2.x, w2.y)); fma2(acc[5], aa, pk2(w2.z, w2.w));
            fma2(acc[6], aa, pk2(w3.x, w3.y)); fma2(acc[7], aa, pk2(w3.z, w3.w));
        }
        float* op = s_fl + e * 32 + co;
#pragma unroll
        for (int c = 0; c < 8; ++c) {
            float lo, hi;
            up2(acc[c], lo, hi);
            op[c * 2] = lo; op[c * 2 + 1] = hi;
        }
    }
    __syncthreads();
    if (t < EPG) {
        int e = t, rev = revloc(e);
        const float* pe = s_fl + e * 32;
        const float* pr = s_fl + rev * 32;
        float l0 = bc[0], l1 = bc[1];
#pragma unroll 8
        for (int c = 0; c < 32; ++c) {
            float p = pe[c] * pr[c];
            l0 += p * s_Wc[c * 2];
            l1 += p * s_Wc[c * 2 + 1];
        }
        int ge = g * EPG + e, grev = g * EPG + rev;
        int mn = min(ge, grev);
        float y0 = l0 + noise[2 * mn];
        float y1 = l1 + noise[2 * mn + 1];
        float fl = (y0 >= y1) ? 1.f : 0.f;
        d_flag[ge] = fl;
        if (fl != 0.f) {
            int p = atomicAdd(&d_cnt, 1);
            d_list[p] = ge;
        }
    }
}

// ---- K3: tf32 tensor-core GEMM over flag-1 edges: d_fc[e] = ef[e] @ W[:,0:1024] + gc ----
#define GEMM_SMEM (128 * 132 * 4 + 128 * 4)
__global__ void __launch_bounds__(256) gemm_k(const float* __restrict__ ef) {
    extern __shared__ __align__(16) float gsm[];
    float* As = gsm;                       // 128 rows x 132 (tf32 bits)
    int* sIdx = (int*)(gsm + 128 * 132);
    int cnt = d_cnt;
    int bm = blockIdx.y * 128;
    if (bm >= cnt) return;
    int nt = blockIdx.x;
    int t = threadIdx.x;
    if (t < 128) sIdx[t] = d_list[min(bm + t, cnt - 1)];
    __syncthreads();
    for (int i = t; i < 4096; i += 256) {
        int row = i >> 5, q = i & 31;
        float4 v = *(const float4*)(ef + sIdx[row] * 128 + q * 4);
        float4 w = make_float4(__uint_as_float(to_tf32(v.x)), __uint_as_float(to_tf32(v.y)),
                               __uint_as_float(to_tf32(v.z)), __uint_as_float(to_tf32(v.w)));
        *(float4*)(As + row * 132 + q * 4) = w;
    }
    __syncthreads();
    int lane = t & 31, warp = t >> 5;
    int wm = warp & 3, wn = warp >> 2;
    const float* arow0 = As + (wm * 32 + (lane >> 2)) * 132 + (lane & 3);
    float acc[2][8][4];
#pragma unroll
    for (int a = 0; a < 2; ++a)
#pragma unroll
        for (int f = 0; f < 8; ++f)
#pragma unroll
            for (int j = 0; j < 4; ++j) acc[a][f][j] = 0.f;
    const float4* wt = (const float4*)d_Wt + (((nt * 16) * 2 + wn) * 32 + lane) * 4;
    float4 bq[4];
#pragma unroll
    for (int j = 0; j < 4; ++j) bq[j] = wt[j];
#pragma unroll
    for (int ks = 0; ks < 16; ++ks) {
        uint32_t br[16];
        br[0]  = __float_as_uint(bq[0].x); br[1]  = __float_as_uint(bq[0].y);
        br[2]  = __float_as_uint(bq[0].z); br[3]  = __float_as_uint(bq[0].w);
        br[4]  = __float_as_uint(bq[1].x); br[5]  = __float_as_uint(bq[1].y);
        br[6]  = __float_as_uint(bq[1].z); br[7]  = __float_as_uint(bq[1].w);
        br[8]  = __float_as_uint(bq[2].x); br[9]  = __float_as_uint(bq[2].y);
        br[10] = __float_as_uint(bq[2].z); br[11] = __float_as_uint(bq[2].w);
        br[12] = __float_as_uint(bq[3].x); br[13] = __float_as_uint(bq[3].y);
        br[14] = __float_as_uint(bq[3].z); br[15] = __float_as_uint(bq[3].w);
        if (ks < 15) {
            const float4* nxt = wt + (ks + 1) * 256;
#pragma unroll
            for (int j = 0; j < 4; ++j) bq[j] = nxt[j];
        }
        const float* ap = arow0 + ks * 8;
        uint32_t a0[4], a1[4];
        a0[0] = __float_as_uint(ap[0]);
        a0[1] = __float_as_uint(ap[8 * 132]);
        a0[2] = __float_as_uint(ap[4]);
        a0[3] = __float_as_uint(ap[8 * 132 + 4]);
        const float* ap1 = ap + 16 * 132;
        a1[0] = __float_as_uint(ap1[0]);
        a1[1] = __float_as_uint(ap1[8 * 132]);
        a1[2] = __float_as_uint(ap1[4]);
        a1[3] = __float_as_uint(ap1[8 * 132 + 4]);
#pragma unroll
        for (int f = 0; f < 8; ++f) {
            mma_tf32(acc[0][f], a0, br[f * 2], br[f * 2 + 1]);
            mma_tf32(acc[1][f], a1, br[f * 2], br[f * 2 + 1]);
        }
    }
    int gr = lane >> 2, qc = (lane & 3) * 2;
#pragma unroll
    for (int mf = 0; mf < 2; ++mf) {
#pragma unroll
        for (int rr = 0; rr < 2; ++rr) {
            int lrow = wm * 32 + mf * 16 + gr + rr * 8;
            int slot = bm + lrow;
            if (slot < cnt) {
                int e = sIdx[lrow];
                int g = e / EPG;
                const float* gcb = d_gc + g * NC;
                float* fcb = d_fc + e * 1024;
#pragma unroll
                for (int f = 0; f < 8; ++f) {
                    int col = nt * 128 + wn * 64 + f * 8 + qc;
                    float2 gv = *(const float2*)(gcb + col);
                    float2 ov;
                    ov.x = acc[mf][f][rr * 2 + 0] + gv.x;
                    ov.y = acc[mf][f][rr * 2 + 1] + gv.y;
                    *(float2*)(fcb + col) = ov;
                }
            }
        }
    }
}

// ---- K4: einsum over flag-1 edges ----
__global__ void einsum_k() {
    __shared__ __align__(16) float sE[4 * 1056];
    __shared__ __align__(16) float sR[4 * 1024];
    __shared__ int sID[4];
    int cnt = d_cnt;
    int base = blockIdx.x * 4;
    if (base >= cnt) return;
    int t = threadIdx.x;
    if (t < 4) sID[t] = d_list[min(base + t, cnt - 1)];
    __syncthreads();
#pragma unroll
    for (int i = 0; i < 16; ++i) {
        int idx = i * 128 + t;
        int side = idx >> 10, rem = idx & 1023;
        int le = rem >> 8, j = (rem & 255) * 4;
        int e = sID[le];
        int mat = j >> 9, w = j & 511, a2 = w >> 5, m = w & 31;
        if (side == 0) {
            float4 v = *(const float4*)(d_fc + e * 1024 + j);
            float* p = sE + le * 1056 + mat * 528 + a2 * 33 + m;
            p[0] = v.x; p[1] = v.y; p[2] = v.z; p[3] = v.w;
        } else {
            int g = e / EPG, ee = e - g * EPG;
            int r = g * EPG + revloc(ee);
            float4 v = *(const float4*)(d_fc + r * 1024 + j);
            float* p = sR + le * 1024 + mat * 512 + m * 16 + a2;
            p[0] = v.x; p[16] = v.y; p[32] = v.z; p[48] = v.w;
        }
    }
    __syncthreads();
    int le = t >> 5, lane = t & 31, a = lane & 15, half = lane >> 4;
    if (base + le >= cnt) return;
    int e = sID[le];
#pragma unroll
    for (int mat = 0; mat < 2; ++mat) {
        const float* Er = sE + le * 1056 + mat * 528 + a * 33;
        const float* Rr = sR + le * 1024 + mat * 512 + half * 8;
        unsigned long long acc[4];
#pragma unroll
        for (int j = 0; j < 4; ++j) acc[j] = 0ULL;
#pragma unroll
        for (int m = 0; m < 32; ++m) {
            float va = Er[m];
            unsigned long long aa = pk2(va, va);
            float4 r0 = *(const float4*)(Rr + m * 16);
            float4 r1 = *(const float4*)(Rr + m * 16 + 4);
            fma2(acc[0], aa, pk2(r0.x, r0.y)); fma2(acc[1], aa, pk2(r0.z, r0.w));
            fma2(acc[2], aa, pk2(r1.x, r1.y)); fma2(acc[3], aa, pk2(r1.z, r1.w));
        }
        float o0, o1, o2, o3, o4, o5, o6, o7;
        up2(acc[0], o0, o1); up2(acc[1], o2, o3);
        up2(acc[2], o4, o5); up2(acc[3], o6, o7);
        float* op = (mat ? d_uv : d_fv) + e * 256 + a * 16 + half * 8;
        *(float4*)op = make_float4(o0, o1, o2, o3);
        *(float4*)(op + 4) = make_float4(o4, o5, o6, o7);
    }
}

// ---- K5: BP, one CTA per graph, 512 threads, fv cached in dynamic smem ----
__global__ void __launch_bounds__(512) bp_k(float* __restrict__ out) {
    extern __shared__ __align__(16) float sm[];
    float* s_fv = sm;                      // 132*256
    float* sA   = sm + 33792;              // 2112
    float* sB   = sA + 2112;
    float* uA   = sB + 2112;
    float* uB   = uA + 2112;
    float* s_mm = uB + 2112;               // 192
    float* s_um = s_mm + 192;
    float* s_if = s_um + 192;
    float* s_iu = s_if + 192;
    int*   s_act = (int*)(s_iu + 192);     // 132
    int*   s_cntp = s_act + 132;

    int g = blockIdx.x, t = threadIdx.x;
    if (t == 0) *s_cntp = 0;
    for (int i = t; i < 2112; i += 512) { sA[i] = 0.f; sB[i] = 0.f; uA[i] = 0.f; uB[i] = 0.f; }
    if (t < 192) {
        float fi = d_if[g * 192 + t], ui = d_iu[g * 192 + t];
        s_if[t] = fi; s_iu[t] = ui;
        s_mm[t] = fi; s_um[t] = ui;
    }
    __syncthreads();
    if (t < EPG && d_flag[g * EPG + t] != 0.f) {
        int p = atomicAdd(s_cntp, 1);
        s_act[p] = t;
    }
    __syncthreads();
    int cnt = *s_cntp;
    int cnt16 = cnt * 16;
    for (int i = t; i < cnt * 64; i += 512) {
        int p = i >> 6, c = i & 63;
        int a = c >> 2, q = c & 3;
        int e = s_act[p];
        float4 v = *(const float4*)(d_fv + (g * EPG + e) * 256 + c * 4);
        int sw = a * 4 + (q ^ (a >> 2));
        *(float4*)(s_fv + p * 256 + sw * 4) = v;
    }
    __syncthreads();

    for (int it = 0; it < NPG; ++it) {
        const float* om = (it & 1) ? sB : sA;
        const float* ou = (it & 1) ? uB : uA;
        float* nm = (it & 1) ? sA : sB;
        float* nu = (it & 1) ? uA : uB;
        for (int idx = t; idx < cnt16; idx += 512) {
            int p = idx >> 4;
            int e = s_act[p];
            int a = idx & 15;
            unsigned mask = (t & 16) ? 0xFFFF0000u : 0x0000FFFFu;
            int s = e / 11;
            int rev = revloc(e);
            int ge = g * EPG + e;
            const float* fvb = s_fv + p * 256;
            int ax4 = a * 4, ash = a >> 2;
            float4 f0 = *(const float4*)(fvb + (ax4 + (0 ^ ash)) * 4);
            float4 f1 = *(const float4*)(fvb + (ax4 + (1 ^ ash)) * 4);
            float4 f2 = *(const float4*)(fvb + (ax4 + (2 ^ ash)) * 4);
            float4 f3 = *(const float4*)(fvb + (ax4 + (3 ^ ash)) * 4);
            const float4* uvp = (const float4*)(d_uv + ge * 256 + a * 16);
            float4 u0 = uvp[0], u1 = uvp[1], u2 = uvp[2], u3 = uvp[3];
            float fv[16] = {f0.x, f0.y, f0.z, f0.w, f1.x, f1.y, f1.z, f1.w,
                            f2.x, f2.y, f2.z, f2.w, f3.x, f3.y, f3.z, f3.w};
            float uv[16] = {u0.x, u0.y, u0.z, u0.w, u1.x, u1.y, u1.z, u1.w,
                            u2.x, u2.y, u2.z, u2.w, u3.x, u3.y, u3.z, u3.w};
            float m[16], mx = -1e30f;
#pragma unroll
            for (int b = 0; b < 16; ++b) {
                float agg = s_mm[s * 16 + b] - om[rev * 16 + b];
                m[b] = fv[b] + agg;
                mx = fmaxf(mx, m[b]);
            }
            float se = 0.f;
#pragma unroll
            for (int b = 0; b < 16; ++b) {
                float pb = __expf(m[b] - mx);
                m[b] = pb;
                se += pb;
            }
            float lse = mx + __logf(se);
            float gm = lse;
#pragma unroll
            for (int w = 8; w > 0; w >>= 1) gm = fmaxf(gm, __shfl_xor_sync(mask, gm, w));
            float gs = __expf(lse - gm);
#pragma unroll
            for (int w = 8; w > 0; w >>= 1) gs += __shfl_xor_sync(mask, gs, w);
            float GL = gm + __logf(gs);
            nm[e * 16 + a] = lse - GL;
            float acc = 0.f;
#pragma unroll
            for (int b = 0; b < 16; ++b) {
                float util = s_um[s * 16 + b] - ou[rev * 16 + b];
                acc += (uv[b] + util) * m[b];
            }
            nu[e * 16 + a] = acc * __fdividef(1.f, se);
        }
        __syncthreads();
        if (t < 192) {
            int n = t >> 4, b = t & 15;
            float am = 0.f, au = 0.f;
#pragma unroll
            for (int s2 = 0; s2 < NPG; ++s2) {
                if (s2 == n) continue;
                int ee = s2 * 11 + n - (n > s2);
                am += nm[ee * 16 + b];
                au += nu[ee * 16 + b];
            }
            s_mm[t] = am + s_if[t];
            s_um[t] = au + s_iu[t];
        }
        __syncthreads();
    }
    if (t < 16) out[g * 16 + t] = s_um[t];
}

#define BP_SMEM ((33792 + 4 * 2112 + 4 * 192) * 4 + 136 * 4)

extern "C" void kernel_launch(void* const* d_in, const int* in_sizes, int n_in,
                              void* d_out, int out_size) {
    const float* ef   = (const float*)d_in[0];
    const float* nf   = (const float*)d_in[1];
    const float* gf   = (const float*)d_in[2];
    const float* gn   = (const float*)d_in[7];
    const float* Wjf  = (const float*)d_in[8];
    const float* bjf  = (const float*)d_in[9];
    const float* Wif  = (const float*)d_in[10];
    const float* bif  = (const float*)d_in[11];
    const float* Wju  = (const float*)d_in[12];
    const float* bju  = (const float*)d_in[13];
    const float* Wiu  = (const float*)d_in[14];
    const float* biu  = (const float*)d_in[15];
    const float* Wfl  = (const float*)d_in[16];
    const float* bfl  = (const float*)d_in[17];
    const float* Wcls = (const float*)d_in[18];
    const float* bcls = (const float*)d_in[19];
    float* out = (float*)d_out;

    static int attr_set = 0;
    if (!attr_set) {
        cudaFuncSetAttribute(flvflag_k, cudaFuncAttributeMaxDynamicSharedMemorySize, FLV_SMEM);
        cudaFuncSetAttribute(gemm_k, cudaFuncAttributeMaxDynamicSharedMemorySize, GEMM_SMEM);
        cudaFuncSetAttribute(bp_k, cudaFuncAttributeMaxDynamicSharedMemorySize, BP_SMEM);
        attr_set = 1;
    }

    prep_k<<<1232, 256>>>(Wjf, bjf, Wju, bju, Wfl, bfl, gf, nf, Wif, bif, Wiu, biu);
    flvflag_k<<<B_, FLV_THREADS, FLV_SMEM>>>(ef, Wfl, gn, Wcls, bcls);
    gemm_k<<<dim3(8, 132), 256, GEMM_SMEM>>>(ef);
    einsum_k<<<E_TOT / 4, 128>>>();
    bp_k<<<B_, 512, BP_SMEM>>>(out);
}

// round 9
// speedup vs baseline: 2.4050x; 1.1002x over previous
#include <cuda_runtime.h>
#include <cstdint>

#define B_    128
#define NPG   12
#define EPG   132
#define E_TOT 16896
#define NT    1536
#define NC    1056   // 512 jf | 512 ju | 32 fl (in d_gc)

__device__ float d_Wt[131072];         // tf32-prerounded, fragment-swizzled
__device__ float d_gc[B_ * NC];
__device__ float d_fc[E_TOT * 1024];   // jf|ju rows, only flag-1 edges valid
__device__ float d_fv[E_TOT * 256];
__device__ float d_uv[E_TOT * 256];
__device__ float d_flag[E_TOT];
__device__ float d_if[NT * 16];
__device__ float d_iu[NT * 16];
__device__ int   d_cnt;
__device__ int   d_pcnt;
__device__ int   d_list[E_TOT];
__device__ int   d_plist[E_TOT / 2];

__device__ __forceinline__ unsigned long long pk2(float lo, float hi) {
    unsigned long long r;
    asm("mov.b64 %0, {%1, %2};" : "=l"(r) : "f"(lo), "f"(hi));
    return r;
}
__device__ __forceinline__ void fma2(unsigned long long& d, unsigned long long a, unsigned long long b) {
    asm("fma.rn.f32x2 %0, %1, %2, %0;" : "+l"(d) : "l"(a), "l"(b));
}
__device__ __forceinline__ void up2(unsigned long long v, float& lo, float& hi) {
    asm("mov.b64 {%0, %1}, %2;" : "=f"(lo), "=f"(hi) : "l"(v));
}
__device__ __forceinline__ int revloc(int ee) {
    int s = ee / 11, dd = ee - s * 11;
    int d = dd + (dd >= s);
    return d * 11 + s - (s > d);
}
__device__ __forceinline__ void mma_tf32(float* d, const uint32_t* a, uint32_t b0, uint32_t b1) {
    asm volatile("mma.sync.aligned.m16n8k8.row.col.f32.tf32.tf32.f32 "
        "{%0,%1,%2,%3}, {%4,%5,%6,%7}, {%8,%9}, {%0,%1,%2,%3};\n"
        : "+f"(d[0]), "+f"(d[1]), "+f"(d[2]), "+f"(d[3])
        : "r"(a[0]), "r"(a[1]), "r"(a[2]), "r"(a[3]), "r"(b0), "r"(b1));
}
__device__ __forceinline__ uint32_t to_tf32(float v) {
    uint32_t r;
    asm("cvt.rna.tf32.f32 %0, %1;" : "=r"(r) : "f"(v));
    return r;
}

// ---- K1: fused prep: Wt pack (blocks 0..511) | gc (512..1039) | node lin (1040..1231) ----
__global__ void __launch_bounds__(256) prep_k(
        const float* __restrict__ Wjf, const float* __restrict__ bjf,
        const float* __restrict__ Wju, const float* __restrict__ bju,
        const float* __restrict__ Wfl, const float* __restrict__ bfl,
        const float* __restrict__ gf,  const float* __restrict__ nf,
        const float* __restrict__ Wif, const float* __restrict__ bif,
        const float* __restrict__ Wiu, const float* __restrict__ biu) {
    __shared__ float xn[8][128];
    int b = blockIdx.x, t = threadIdx.x;
    if (b == 0 && t == 0) { d_cnt = 0; d_pcnt = 0; }
    if (b < 512) {
        int i = b * 256 + t;
        int r = i & 1, f = (i >> 1) & 7, lane = (i >> 4) & 31;
        int wn = (i >> 9) & 1, ks = (i >> 10) & 15, nt = (i >> 14) & 7;
        int j = nt * 128 + wn * 64 + f * 8 + (lane >> 2);
        int k = ks * 8 + (lane & 3) + r * 4;
        float v = (j < 512) ? Wjf[k * 512 + j] : Wju[k * 512 + j - 512];
        d_Wt[i] = __uint_as_float(to_tf32(v));
    } else if (b < 1040) {
        int i = (b - 512) * 256 + t;
        int g = i / NC, j = i - g * NC;
        const float* Wp; int st; float acc;
        if (j < 512)        { Wp = Wjf + 128 * 512 + j;          st = 512; acc = bjf[j]; }
        else if (j < 1024)  { Wp = Wju + 128 * 512 + (j - 512);  st = 512; acc = bju[j - 512]; }
        else                { Wp = Wfl + 128 * 32  + (j - 1024); st = 32;  acc = bfl[j - 1024]; }
        const float* gr = gf + g * 64;
#pragma unroll 8
        for (int k = 0; k < 64; ++k) acc += gr[k] * Wp[k * st];
        d_gc[i] = acc;
    } else {
        int nb = (b - 1040) * 8;
        for (int i = t; i < 1024; i += 256) {
            int node = i >> 7, kk = i & 127;
            xn[node][kk] = (kk < 64) ? nf[(nb + node) * 64 + kk]
                                     : gf[((nb + node) / NPG) * 64 + kk - 64];
        }
        __syncthreads();
        int w = t >> 5, lane = t & 31;
        int n = nb + w;
        const float* W = (lane < 16) ? Wif : Wiu;
        int col = lane & 15;
        float acc = (lane < 16) ? bif[col] : biu[col];
#pragma unroll 8
        for (int k = 0; k < 128; ++k) acc += xn[w][k] * W[k * 16 + col];
        if (lane < 16) d_if[n * 16 + col] = acc;
        else           d_iu[n * 16 + col] = acc;
    }
}

// ---- K2: fused fl-linear + gumbel flag + compaction, one CTA per graph ----
#define FLV_THREADS 264
#define FLV_SMEM ((132 * 132 + 128 * 32 + 132 * 32 + 64) * 4)
__global__ void __launch_bounds__(FLV_THREADS) flvflag_k(
        const float* __restrict__ ef, const float* __restrict__ Wfl,
        const float* __restrict__ noise, const float* __restrict__ Wc,
        const float* __restrict__ bc) {
    extern __shared__ __align__(16) float fsm[];
    float* s_ef = fsm;                      // 132 rows x 132 (128 used)
    float* s_W  = fsm + 132 * 132;          // 128 x 32
    float* s_fl = s_W + 128 * 32;           // 132 x 32
    float* s_Wc = s_fl + 132 * 32;          // 64
    int g = blockIdx.x, t = threadIdx.x;
    for (int i = t; i < 4224; i += FLV_THREADS) {
        int r = i >> 5, q = i & 31;
        float4 v = *(const float4*)(ef + (g * EPG + r) * 128 + q * 4);
        *(float4*)(s_ef + r * 132 + q * 4) = v;
    }
    for (int i = t; i < 1024; i += FLV_THREADS)
        *(float4*)(s_W + i * 4) = *(const float4*)(Wfl + i * 4);
    if (t < 64) s_Wc[t] = Wc[t];
    __syncthreads();
    {
        int e = t >> 1, co = (t & 1) * 16;
        unsigned long long acc[8];
        const float* gb = d_gc + g * NC + 1024 + co;
#pragma unroll
        for (int c = 0; c < 8; ++c) acc[c] = pk2(gb[c * 2], gb[c * 2 + 1]);
        const float* er = s_ef + e * 132;
#pragma unroll 4
        for (int k = 0; k < 128; ++k) {
            float a = er[k];
            unsigned long long aa = pk2(a, a);
            const float4* wr = (const float4*)(s_W + k * 32 + co);
            float4 w0 = wr[0], w1 = wr[1], w2 = wr[2], w3 = wr[3];
            fma2(acc[0], aa, pk2(w0.x, w0.y)); fma2(acc[1], aa, pk2(w0.z, w0.w));
            fma2(acc[2], aa, pk2(w1.x, w1.y)); fma2(acc[3], aa, pk2(w1.z, w1.w));
            fma2(acc[4], aa, pk2(w2.x, w2.y)); fma2(acc[5], aa, pk2(w2.z, w2.w));
            fma2(acc[6], aa, pk2(w3.x, w3.y)); fma2(acc[7], aa, pk2(w3.z, w3.w));
        }
        float* op = s_fl + e * 32 + co;
#pragma unroll
        for (int c = 0; c < 8; ++c) {
            float lo, hi;
            up2(acc[c], lo, hi);
            op[c * 2] = lo; op[c * 2 + 1] = hi;
        }
    }
    __syncthreads();
    if (t < EPG) {
        int e = t, rev = revloc(e);
        const float* pe = s_fl + e * 32;
        const float* pr = s_fl + rev * 32;
        float l0 = bc[0], l1 = bc[1];
#pragma unroll 8
        for (int c = 0; c < 32; ++c) {
            float p = pe[c] * pr[c];
            l0 += p * s_Wc[c * 2];
            l1 += p * s_Wc[c * 2 + 1];
        }
        int ge = g * EPG + e, grev = g * EPG + rev;
        int mn = min(ge, grev);
        float y0 = l0 + noise[2 * mn];
        float y1 = l1 + noise[2 * mn + 1];
        float fl = (y0 >= y1) ? 1.f : 0.f;
        d_flag[ge] = fl;
        if (fl != 0.f) {
            int p = atomicAdd(&d_cnt, 1);
            d_list[p] = ge;
            if (e < rev) {
                int pp = atomicAdd(&d_pcnt, 1);
                d_plist[pp] = ge;
            }
        }
    }
}

// ---- K3: tf32 tensor-core GEMM over flag-1 edges ----
#define GEMM_SMEM (128 * 132 * 4 + 128 * 4)
__global__ void __launch_bounds__(256) gemm_k(const float* __restrict__ ef) {
    extern __shared__ __align__(16) float gsm[];
    float* As = gsm;                       // 128 rows x 132
    int* sIdx = (int*)(gsm + 128 * 132);
    int cnt = d_cnt;
    int bm = blockIdx.y * 128;
    if (bm >= cnt) return;
    int nt = blockIdx.x;
    int t = threadIdx.x;
    if (t < 128) sIdx[t] = d_list[min(bm + t, cnt - 1)];
    __syncthreads();
    for (int i = t; i < 4096; i += 256) {
        int row = i >> 5, q = i & 31;
        float4 v = *(const float4*)(ef + sIdx[row] * 128 + q * 4);
        float4 w = make_float4(__uint_as_float(to_tf32(v.x)), __uint_as_float(to_tf32(v.y)),
                               __uint_as_float(to_tf32(v.z)), __uint_as_float(to_tf32(v.w)));
        *(float4*)(As + row * 132 + q * 4) = w;
    }
    __syncthreads();
    int lane = t & 31, warp = t >> 5;
    int wm = warp & 3, wn = warp >> 2;
    const float* arow0 = As + (wm * 32 + (lane >> 2)) * 132 + (lane & 3);
    float acc[2][8][4];
#pragma unroll
    for (int a = 0; a < 2; ++a)
#pragma unroll
        for (int f = 0; f < 8; ++f)
#pragma unroll
            for (int j = 0; j < 4; ++j) acc[a][f][j] = 0.f;
    const float4* wt = (const float4*)d_Wt + (((nt * 16) * 2 + wn) * 32 + lane) * 4;
    float4 bq[4];
#pragma unroll
    for (int j = 0; j < 4; ++j) bq[j] = wt[j];
#pragma unroll
    for (int ks = 0; ks < 16; ++ks) {
        uint32_t br[16];
        br[0]  = __float_as_uint(bq[0].x); br[1]  = __float_as_uint(bq[0].y);
        br[2]  = __float_as_uint(bq[0].z); br[3]  = __float_as_uint(bq[0].w);
        br[4]  = __float_as_uint(bq[1].x); br[5]  = __float_as_uint(bq[1].y);
        br[6]  = __float_as_uint(bq[1].z); br[7]  = __float_as_uint(bq[1].w);
        br[8]  = __float_as_uint(bq[2].x); br[9]  = __float_as_uint(bq[2].y);
        br[10] = __float_as_uint(bq[2].z); br[11] = __float_as_uint(bq[2].w);
        br[12] = __float_as_uint(bq[3].x); br[13] = __float_as_uint(bq[3].y);
        br[14] = __float_as_uint(bq[3].z); br[15] = __float_as_uint(bq[3].w);
        if (ks < 15) {
            const float4* nxt = wt + (ks + 1) * 256;
#pragma unroll
            for (int j = 0; j < 4; ++j) bq[j] = nxt[j];
        }
        const float* ap = arow0 + ks * 8;
        uint32_t a0[4], a1[4];
        a0[0] = __float_as_uint(ap[0]);
        a0[1] = __float_as_uint(ap[8 * 132]);
        a0[2] = __float_as_uint(ap[4]);
        a0[3] = __float_as_uint(ap[8 * 132 + 4]);
        const float* ap1 = ap + 16 * 132;
        a1[0] = __float_as_uint(ap1[0]);
        a1[1] = __float_as_uint(ap1[8 * 132]);
        a1[2] = __float_as_uint(ap1[4]);
        a1[3] = __float_as_uint(ap1[8 * 132 + 4]);
#pragma unroll
        for (int f = 0; f < 8; ++f) {
            mma_tf32(acc[0][f], a0, br[f * 2], br[f * 2 + 1]);
            mma_tf32(acc[1][f], a1, br[f * 2], br[f * 2 + 1]);
        }
    }
    int gr = lane >> 2, qc = (lane & 3) * 2;
#pragma unroll
    for (int mf = 0; mf < 2; ++mf) {
#pragma unroll
        for (int rr = 0; rr < 2; ++rr) {
            int lrow = wm * 32 + mf * 16 + gr + rr * 8;
            int slot = bm + lrow;
            if (slot < cnt) {
                int e = sIdx[lrow];
                int g = e / EPG;
                const float* gcb = d_gc + g * NC;
                float* fcb = d_fc + e * 1024;
#pragma unroll
                for (int f = 0; f < 8; ++f) {
                    int col = nt * 128 + wn * 64 + f * 8 + qc;
                    float2 gv = *(const float2*)(gcb + col);
                    float2 ov;
                    ov.x = acc[mf][f][rr * 2 + 0] + gv.x;
                    ov.y = acc[mf][f][rr * 2 + 1] + gv.y;
                    *(float2*)(fcb + col) = ov;
                }
            }
        }
    }
}

// ---- K4: tensor-core einsum over flag-1 PAIRS; writes e and rev (transposed) ----
#define EIN_SMEM (8 * 4 * 576 * 4)
__global__ void __launch_bounds__(256) einsum_k() {
    extern __shared__ __align__(16) float esm[];
    int pcnt = d_pcnt;
    int t = threadIdx.x, warp = t >> 5, lane = t & 31;
    int p = blockIdx.x * 8 + warp;
    if (p >= pcnt) return;
    int e = d_plist[p];
    int g = e / EPG, ee = e - g * EPG;
    int rv = g * EPG + revloc(ee);
    float* sm0 = esm + warp * 2304;  // 4 matrices x 576 (16x36)
    const float* src0 = d_fc + e * 1024;
    const float* src1 = d_fc + rv * 1024;
#pragma unroll
    for (int i = 0; i < 8; ++i) {
        int j = i * 128 + lane * 4;
        int mat = j >> 9, a = (j >> 5) & 15, m = j & 31;
        float4 v0 = *(const float4*)(src0 + j);
        *(float4*)(sm0 + mat * 576 + a * 36 + m) = v0;
        float4 v1 = *(const float4*)(src1 + j);
        *(float4*)(sm0 + (mat + 2) * 576 + a * 36 + m) = v1;
    }
    __syncwarp();
    int r = lane >> 2, cb = lane & 3;
#pragma unroll
    for (int mat = 0; mat < 2; ++mat) {
        const float* Ae = sm0 + mat * 576;
        const float* Ar = sm0 + (mat + 2) * 576;
        float acc[2][4];
#pragma unroll
        for (int nf = 0; nf < 2; ++nf)
#pragma unroll
            for (int j = 0; j < 4; ++j) acc[nf][j] = 0.f;
#pragma unroll
        for (int ks = 0; ks < 4; ++ks) {
            const float* ap = Ae + r * 36 + ks * 8 + cb;
            uint32_t a[4];
            a[0] = __float_as_uint(ap[0]);
            a[1] = __float_as_uint(ap[8 * 36]);
            a[2] = __float_as_uint(ap[4]);
            a[3] = __float_as_uint(ap[8 * 36 + 4]);
#pragma unroll
            for (int nf = 0; nf < 2; ++nf) {
                const float* bp = Ar + (nf * 8 + r) * 36 + ks * 8 + cb;
                uint32_t b0 = __float_as_uint(bp[0]);
                uint32_t b1 = __float_as_uint(bp[4]);
                mma_tf32(acc[nf], a, b0, b1);
            }
        }
        float* fe = (mat ? d_uv : d_fv) + e * 256;
        float* fr = (mat ? d_uv : d_fv) + rv * 256;
#pragma unroll
        for (int nf = 0; nf < 2; ++nf) {
            int b = nf * 8 + cb * 2;
            *(float2*)(fe + r * 16 + b) = make_float2(acc[nf][0], acc[nf][1]);
            *(float2*)(fe + (r + 8) * 16 + b) = make_float2(acc[nf][2], acc[nf][3]);
            fr[b * 16 + r]           = acc[nf][0];
            fr[(b + 1) * 16 + r]     = acc[nf][1];
            fr[b * 16 + r + 8]       = acc[nf][2];
            fr[(b + 1) * 16 + r + 8] = acc[nf][3];
        }
    }
}

// ---- K5: BP, one CTA per graph, 512 threads, fv+uv cached in dynamic smem ----
#define CAP 90
__global__ void __launch_bounds__(512) bp_k(float* __restrict__ out) {
    extern __shared__ __align__(16) float sm[];
    float* s_dat = sm;                     // CAP*512: per edge p: fv[256]|uv[256], swizzled
    float* sA   = sm + CAP * 512;          // 2112
    float* sB   = sA + 2112;
    float* uA   = sB + 2112;
    float* uB   = uA + 2112;
    float* s_mm = uB + 2112;               // 192
    float* s_um = s_mm + 192;
    float* s_if = s_um + 192;
    float* s_iu = s_if + 192;
    int*   s_act = (int*)(s_iu + 192);     // 132
    int*   s_cntp = s_act + 132;

    int g = blockIdx.x, t = threadIdx.x;
    if (t == 0) *s_cntp = 0;
    for (int i = t; i < 2112; i += 512) { sA[i] = 0.f; sB[i] = 0.f; uA[i] = 0.f; uB[i] = 0.f; }
    if (t < 192) {
        float fi = d_if[g * 192 + t], ui = d_iu[g * 192 + t];
        s_if[t] = fi; s_iu[t] = ui;
        s_mm[t] = fi; s_um[t] = ui;
    }
    __syncthreads();
    if (t < EPG && d_flag[g * EPG + t] != 0.f) {
        int p = atomicAdd(s_cntp, 1);
        s_act[p] = t;
    }
    __syncthreads();
    int cnt = *s_cntp;
    int cnt16 = cnt * 16;
    int lim = min(cnt, CAP);
    for (int i = t; i < lim * 128; i += 512) {
        int p = i >> 7, c = i & 127;
        int tens = c >> 6, cc = c & 63;
        int a = cc >> 2, q = cc & 3;
        int e = s_act[p];
        const float* src = (tens ? d_uv : d_fv) + (g * EPG + e) * 256 + cc * 4;
        float4 v = *(const float4*)src;
        int sw = a * 4 + (q ^ (a >> 2));
        *(float4*)(s_dat + p * 512 + tens * 256 + sw * 4) = v;
    }
    __syncthreads();

    for (int it = 0; it < NPG; ++it) {
        const float* om = (it & 1) ? sB : sA;
        const float* ou = (it & 1) ? uB : uA;
        float* nm = (it & 1) ? sA : sB;
        float* nu = (it & 1) ? uA : uB;
        for (int idx = t; idx < cnt16; idx += 512) {
            int p = idx >> 4;
            int e = s_act[p];
            int a = idx & 15;
            unsigned mask = (t & 16) ? 0xFFFF0000u : 0x0000FFFFu;
            int s = e / 11;
            int rev = revloc(e);
            float4 f0, f1, f2, f3, u0, u1, u2, u3;
            if (p < CAP) {
                const float* db = s_dat + p * 512;
                int ax4 = a * 4, ash = a >> 2;
                f0 = *(const float4*)(db + (ax4 + (0 ^ ash)) * 4);
                f1 = *(const float4*)(db + (ax4 + (1 ^ ash)) * 4);
                f2 = *(const float4*)(db + (ax4 + (2 ^ ash)) * 4);
                f3 = *(const float4*)(db + (ax4 + (3 ^ ash)) * 4);
                const float* ub = db + 256;
                u0 = *(const float4*)(ub + (ax4 + (0 ^ ash)) * 4);
                u1 = *(const float4*)(ub + (ax4 + (1 ^ ash)) * 4);
                u2 = *(const float4*)(ub + (ax4 + (2 ^ ash)) * 4);
                u3 = *(const float4*)(ub + (ax4 + (3 ^ ash)) * 4);
            } else {
                int ge = g * EPG + e;
                const float4* fvp = (const float4*)(d_fv + ge * 256 + a * 16);
                const float4* uvp = (const float4*)(d_uv + ge * 256 + a * 16);
                f0 = fvp[0]; f1 = fvp[1]; f2 = fvp[2]; f3 = fvp[3];
                u0 = uvp[0]; u1 = uvp[1]; u2 = uvp[2]; u3 = uvp[3];
            }
            float fv[16] = {f0.x, f0.y, f0.z, f0.w, f1.x, f1.y, f1.z, f1.w,
                            f2.x, f2.y, f2.z, f2.w, f3.x, f3.y, f3.z, f3.w};
            float uv[16] = {u0.x, u0.y, u0.z, u0.w, u1.x, u1.y, u1.z, u1.w,
                            u2.x, u2.y, u2.z, u2.w, u3.x, u3.y, u3.z, u3.w};
            float m[16], mx = -1e30f;
#pragma unroll
            for (int b = 0; b < 16; ++b) {
                float agg = s_mm[s * 16 + b] - om[rev * 16 + b];
                m[b] = fv[b] + agg;
                mx = fmaxf(mx, m[b]);
            }
            float se = 0.f;
#pragma unroll
            for (int b = 0; b < 16; ++b) {
                float pb = __expf(m[b] - mx);
                m[b] = pb;
                se += pb;
            }
            float lse = mx + __logf(se);
            float gm = lse;
#pragma unroll
            for (int w = 8; w > 0; w >>= 1) gm = fmaxf(gm, __shfl_xor_sync(mask, gm, w));
            float gs = __expf(lse - gm);
#pragma unroll
            for (int w = 8; w > 0; w >>= 1) gs += __shfl_xor_sync(mask, gs, w);
            float GL = gm + __logf(gs);
            nm[e * 16 + a] = lse - GL;
            float acc = 0.f;
#pragma unroll
            for (int b = 0; b < 16; ++b) {
                float util = s_um[s * 16 + b] - ou[rev * 16 + b];
                acc += (uv[b] + util) * m[b];
            }
            nu[e * 16 + a] = acc * __fdividef(1.f, se);
        }
        __syncthreads();
        if (t < 192) {
            int n = t >> 4, b = t & 15;
            float am = 0.f, au = 0.f;
#pragma unroll
            for (int s2 = 0; s2 < NPG; ++s2) {
                if (s2 == n) continue;
                int ee = s2 * 11 + n - (n > s2);
                am += nm[ee * 16 + b];
                au += nu[ee * 16 + b];
            }
            s_mm[t] = am + s_if[t];
            s_um[t] = au + s_iu[t];
        }
        __syncthreads();
    }
    if (t < 16) out[g * 16 + t] = s_um[t];
}

#define BP_SMEM ((CAP * 512 + 4 * 2112 + 4 * 192) * 4 + 136 * 4)

extern "C" void kernel_launch(void* const* d_in, const int* in_sizes, int n_in,
                              void* d_out, int out_size) {
    const float* ef   = (const float*)d_in[0];
    const float* nf   = (const float*)d_in[1];
    const float* gf   = (const float*)d_in[2];
    const float* gn   = (const float*)d_in[7];
    const float* Wjf  = (const float*)d_in[8];
    const float* bjf  = (const float*)d_in[9];
    const float* Wif  = (const float*)d_in[10];
    const float* bif  = (const float*)d_in[11];
    const float* Wju  = (const float*)d_in[12];
    const float* bju  = (const float*)d_in[13];
    const float* Wiu  = (const float*)d_in[14];
    const float* biu  = (const float*)d_in[15];
    const float* Wfl  = (const float*)d_in[16];
    const float* bfl  = (const float*)d_in[17];
    const float* Wcls = (const float*)d_in[18];
    const float* bcls = (const float*)d_in[19];
    float* out = (float*)d_out;

    static int attr_set = 0;
    if (!attr_set) {
        cudaFuncSetAttribute(flvflag_k, cudaFuncAttributeMaxDynamicSharedMemorySize, FLV_SMEM);
        cudaFuncSetAttribute(gemm_k, cudaFuncAttributeMaxDynamicSharedMemorySize, GEMM_SMEM);
        cudaFuncSetAttribute(einsum_k, cudaFuncAttributeMaxDynamicSharedMemorySize, EIN_SMEM);
        cudaFuncSetAttribute(bp_k, cudaFuncAttributeMaxDynamicSharedMemorySize, BP_SMEM);
        attr_set = 1;
    }

    prep_k<<<1232, 256>>>(Wjf, bjf, Wju, bju, Wfl, bfl, gf, nf, Wif, bif, Wiu, biu);
    flvflag_k<<<B_, FLV_THREADS, FLV_SMEM>>>(ef, Wfl, gn, Wcls, bcls);
    gemm_k<<<dim3(8, 132), 256, GEMM_SMEM>>>(ef);
    einsum_k<<<1056, 256, EIN_SMEM>>>();
    bp_k<<<B_, 512, BP_SMEM>>>(out);
}

// round 10
// speedup vs baseline: 2.4785x; 1.0306x over previous
#include <cuda_runtime.h>
#include <cstdint>

#define B_    128
#define NPG   12
#define EPG   132
#define E_TOT 16896
#define NT    1536
#define NC    1056   // 512 jf | 512 ju | 32 fl (in d_gc)

__device__ float d_Wt[131072];         // tf32-prerounded, fragment-swizzled
__device__ float d_gc[B_ * NC];
__device__ float d_fc[E_TOT * 1024];   // jf|ju rows, only flag-1 edges valid
__device__ float d_fv[E_TOT * 256];
__device__ float d_uv[E_TOT * 256];
__device__ float d_flag[E_TOT];
__device__ float d_if[NT * 16];
__device__ float d_iu[NT * 16];
__device__ int   d_cnt;
__device__ int   d_pcnt;
__device__ int   d_list[E_TOT];
__device__ int   d_plist[E_TOT / 2];

__device__ __forceinline__ unsigned long long pk2(float lo, float hi) {
    unsigned long long r;
    asm("mov.b64 %0, {%1, %2};" : "=l"(r) : "f"(lo), "f"(hi));
    return r;
}
__device__ __forceinline__ void fma2(unsigned long long& d, unsigned long long a, unsigned long long b) {
    asm("fma.rn.f32x2 %0, %1, %2, %0;" : "+l"(d) : "l"(a), "l"(b));
}
__device__ __forceinline__ void up2(unsigned long long v, float& lo, float& hi) {
    asm("mov.b64 {%0, %1}, %2;" : "=f"(lo), "=f"(hi) : "l"(v));
}
__device__ __forceinline__ int revloc(int ee) {
    int s = ee / 11, dd = ee - s * 11;
    int d = dd + (dd >= s);
    return d * 11 + s - (s > d);
}
__device__ __forceinline__ void mma_tf32(float* d, const uint32_t* a, uint32_t b0, uint32_t b1) {
    asm volatile("mma.sync.aligned.m16n8k8.row.col.f32.tf32.tf32.f32 "
        "{%0,%1,%2,%3}, {%4,%5,%6,%7}, {%8,%9}, {%0,%1,%2,%3};\n"
        : "+f"(d[0]), "+f"(d[1]), "+f"(d[2]), "+f"(d[3])
        : "r"(a[0]), "r"(a[1]), "r"(a[2]), "r"(a[3]), "r"(b0), "r"(b1));
}
__device__ __forceinline__ uint32_t to_tf32(float v) {
    uint32_t r;
    asm("cvt.rna.tf32.f32 %0, %1;" : "=r"(r) : "f"(v));
    return r;
}
__device__ __forceinline__ void split_tf32(float v, uint32_t& hi, uint32_t& lo) {
    hi = to_tf32(v);
    lo = to_tf32(v - __uint_as_float(hi));
}

// ---- K1: fused prep: Wt pack (blocks 0..511) | gc (512..1039) | node lin (1040..1231) ----
__global__ void __launch_bounds__(256) prep_k(
        const float* __restrict__ Wjf, const float* __restrict__ bjf,
        const float* __restrict__ Wju, const float* __restrict__ bju,
        const float* __restrict__ Wfl, const float* __restrict__ bfl,
        const float* __restrict__ gf,  const float* __restrict__ nf,
        const float* __restrict__ Wif, const float* __restrict__ bif,
        const float* __restrict__ Wiu, const float* __restrict__ biu) {
    __shared__ float xn[8][128];
    int b = blockIdx.x, t = threadIdx.x;
    if (b == 0 && t == 0) { d_cnt = 0; d_pcnt = 0; }
    if (b < 512) {
        int i = b * 256 + t;
        int r = i & 1, f = (i >> 1) & 7, lane = (i >> 4) & 31;
        int wn = (i >> 9) & 1, ks = (i >> 10) & 15, nt = (i >> 14) & 7;
        int j = nt * 128 + wn * 64 + f * 8 + (lane >> 2);
        int k = ks * 8 + (lane & 3) + r * 4;
        float v = (j < 512) ? Wjf[k * 512 + j] : Wju[k * 512 + j - 512];
        d_Wt[i] = __uint_as_float(to_tf32(v));
    } else if (b < 1040) {
        int i = (b - 512) * 256 + t;
        int g = i / NC, j = i - g * NC;
        const float* Wp; int st; float acc;
        if (j < 512)        { Wp = Wjf + 128 * 512 + j;          st = 512; acc = bjf[j]; }
        else if (j < 1024)  { Wp = Wju + 128 * 512 + (j - 512);  st = 512; acc = bju[j - 512]; }
        else                { Wp = Wfl + 128 * 32  + (j - 1024); st = 32;  acc = bfl[j - 1024]; }
        const float* gr = gf + g * 64;
#pragma unroll 8
        for (int k = 0; k < 64; ++k) acc += gr[k] * Wp[k * st];
        d_gc[i] = acc;
    } else {
        int nb = (b - 1040) * 8;
        for (int i = t; i < 1024; i += 256) {
            int node = i >> 7, kk = i & 127;
            xn[node][kk] = (kk < 64) ? nf[(nb + node) * 64 + kk]
                                     : gf[((nb + node) / NPG) * 64 + kk - 64];
        }
        __syncthreads();
        int w = t >> 5, lane = t & 31;
        int n = nb + w;
        const float* W = (lane < 16) ? Wif : Wiu;
        int col = lane & 15;
        float acc = (lane < 16) ? bif[col] : biu[col];
#pragma unroll 8
        for (int k = 0; k < 128; ++k) acc += xn[w][k] * W[k * 16 + col];
        if (lane < 16) d_if[n * 16 + col] = acc;
        else           d_iu[n * 16 + col] = acc;
    }
}

// ---- K2: fused fl-linear + gumbel flag + compaction, one CTA per graph ----
#define FLV_THREADS 264
#define FLV_SMEM ((132 * 132 + 128 * 32 + 132 * 32 + 64) * 4)
__global__ void __launch_bounds__(FLV_THREADS) flvflag_k(
        const float* __restrict__ ef, const float* __restrict__ Wfl,
        const float* __restrict__ noise, const float* __restrict__ Wc,
        const float* __restrict__ bc) {
    extern __shared__ __align__(16) float fsm[];
    float* s_ef = fsm;                      // 132 rows x 132 (128 used)
    float* s_W  = fsm + 132 * 132;          // 128 x 32
    float* s_fl = s_W + 128 * 32;           // 132 x 32
    float* s_Wc = s_fl + 132 * 32;          // 64
    int g = blockIdx.x, t = threadIdx.x;
    for (int i = t; i < 4224; i += FLV_THREADS) {
        int r = i >> 5, q = i & 31;
        float4 v = *(const float4*)(ef + (g * EPG + r) * 128 + q * 4);
        *(float4*)(s_ef + r * 132 + q * 4) = v;
    }
    for (int i = t; i < 1024; i += FLV_THREADS)
        *(float4*)(s_W + i * 4) = *(const float4*)(Wfl + i * 4);
    if (t < 64) s_Wc[t] = Wc[t];
    __syncthreads();
    {
        int e = t >> 1, co = (t & 1) * 16;
        unsigned long long acc[8];
        const float* gb = d_gc + g * NC + 1024 + co;
#pragma unroll
        for (int c = 0; c < 8; ++c) acc[c] = pk2(gb[c * 2], gb[c * 2 + 1]);
        const float* er = s_ef + e * 132;
#pragma unroll 4
        for (int k = 0; k < 128; ++k) {
            float a = er[k];
            unsigned long long aa = pk2(a, a);
            const float4* wr = (const float4*)(s_W + k * 32 + co);
            float4 w0 = wr[0], w1 = wr[1], w2 = wr[2], w3 = wr[3];
            fma2(acc[0], aa, pk2(w0.x, w0.y)); fma2(acc[1], aa, pk2(w0.z, w0.w));
            fma2(acc[2], aa, pk2(w1.x, w1.y)); fma2(acc[3], aa, pk2(w1.z, w1.w));
            fma2(acc[4], aa, pk2(w2.x, w2.y)); fma2(acc[5], aa, pk2(w2.z, w2.w));
            fma2(acc[6], aa, pk2(w3.x, w3.y)); fma2(acc[7], aa, pk2(w3.z, w3.w));
        }
        float* op = s_fl + e * 32 + co;
#pragma unroll
        for (int c = 0; c < 8; ++c) {
            float lo, hi;
            up2(acc[c], lo, hi);
            op[c * 2] = lo; op[c * 2 + 1] = hi;
        }
    }
    __syncthreads();
    if (t < EPG) {
        int e = t, rev = revloc(e);
        const float* pe = s_fl + e * 32;
        const float* pr = s_fl + rev * 32;
        float l0 = bc[0], l1 = bc[1];
#pragma unroll 8
        for (int c = 0; c < 32; ++c) {
            float p = pe[c] * pr[c];
            l0 += p * s_Wc[c * 2];
            l1 += p * s_Wc[c * 2 + 1];
        }
        int ge = g * EPG + e, grev = g * EPG + rev;
        int mn = min(ge, grev);
        float y0 = l0 + noise[2 * mn];
        float y1 = l1 + noise[2 * mn + 1];
        float fl = (y0 >= y1) ? 1.f : 0.f;
        d_flag[ge] = fl;
        if (fl != 0.f) {
            int p = atomicAdd(&d_cnt, 1);
            d_list[p] = ge;
            if (e < rev) {
                int pp = atomicAdd(&d_pcnt, 1);
                d_plist[pp] = ge;
            }
        }
    }
}

// ---- K3: tf32 tensor-core GEMM over flag-1 edges ----
#define GEMM_SMEM (128 * 132 * 4 + 128 * 4)
__global__ void __launch_bounds__(256) gemm_k(const float* __restrict__ ef) {
    extern __shared__ __align__(16) float gsm[];
    float* As = gsm;                       // 128 rows x 132
    int* sIdx = (int*)(gsm + 128 * 132);
    int cnt = d_cnt;
    int bm = blockIdx.y * 128;
    if (bm >= cnt) return;
    int nt = blockIdx.x;
    int t = threadIdx.x;
    if (t < 128) sIdx[t] = d_list[min(bm + t, cnt - 1)];
    __syncthreads();
    for (int i = t; i < 4096; i += 256) {
        int row = i >> 5, q = i & 31;
        float4 v = *(const float4*)(ef + sIdx[row] * 128 + q * 4);
        float4 w = make_float4(__uint_as_float(to_tf32(v.x)), __uint_as_float(to_tf32(v.y)),
                               __uint_as_float(to_tf32(v.z)), __uint_as_float(to_tf32(v.w)));
        *(float4*)(As + row * 132 + q * 4) = w;
    }
    __syncthreads();
    int lane = t & 31, warp = t >> 5;
    int wm = warp & 3, wn = warp >> 2;
    const float* arow0 = As + (wm * 32 + (lane >> 2)) * 132 + (lane & 3);
    float acc[2][8][4];
#pragma unroll
    for (int a = 0; a < 2; ++a)
#pragma unroll
        for (int f = 0; f < 8; ++f)
#pragma unroll
            for (int j = 0; j < 4; ++j) acc[a][f][j] = 0.f;
    const float4* wt = (const float4*)d_Wt + (((nt * 16) * 2 + wn) * 32 + lane) * 4;
    float4 bq[4];
#pragma unroll
    for (int j = 0; j < 4; ++j) bq[j] = wt[j];
#pragma unroll
    for (int ks = 0; ks < 16; ++ks) {
        uint32_t br[16];
        br[0]  = __float_as_uint(bq[0].x); br[1]  = __float_as_uint(bq[0].y);
        br[2]  = __float_as_uint(bq[0].z); br[3]  = __float_as_uint(bq[0].w);
        br[4]  = __float_as_uint(bq[1].x); br[5]  = __float_as_uint(bq[1].y);
        br[6]  = __float_as_uint(bq[1].z); br[7]  = __float_as_uint(bq[1].w);
        br[8]  = __float_as_uint(bq[2].x); br[9]  = __float_as_uint(bq[2].y);
        br[10] = __float_as_uint(bq[2].z); br[11] = __float_as_uint(bq[2].w);
        br[12] = __float_as_uint(bq[3].x); br[13] = __float_as_uint(bq[3].y);
        br[14] = __float_as_uint(bq[3].z); br[15] = __float_as_uint(bq[3].w);
        if (ks < 15) {
            const float4* nxt = wt + (ks + 1) * 256;
#pragma unroll
            for (int j = 0; j < 4; ++j) bq[j] = nxt[j];
        }
        const float* ap = arow0 + ks * 8;
        uint32_t a0[4], a1[4];
        a0[0] = __float_as_uint(ap[0]);
        a0[1] = __float_as_uint(ap[8 * 132]);
        a0[2] = __float_as_uint(ap[4]);
        a0[3] = __float_as_uint(ap[8 * 132 + 4]);
        const float* ap1 = ap + 16 * 132;
        a1[0] = __float_as_uint(ap1[0]);
        a1[1] = __float_as_uint(ap1[8 * 132]);
        a1[2] = __float_as_uint(ap1[4]);
        a1[3] = __float_as_uint(ap1[8 * 132 + 4]);
#pragma unroll
        for (int f = 0; f < 8; ++f) {
            mma_tf32(acc[0][f], a0, br[f * 2], br[f * 2 + 1]);
            mma_tf32(acc[1][f], a1, br[f * 2], br[f * 2 + 1]);
        }
    }
    int gr = lane >> 2, qc = (lane & 3) * 2;
#pragma unroll
    for (int mf = 0; mf < 2; ++mf) {
#pragma unroll
        for (int rr = 0; rr < 2; ++rr) {
            int lrow = wm * 32 + mf * 16 + gr + rr * 8;
            int slot = bm + lrow;
            if (slot < cnt) {
                int e = sIdx[lrow];
                int g = e / EPG;
                const float* gcb = d_gc + g * NC;
                float* fcb = d_fc + e * 1024;
#pragma unroll
                for (int f = 0; f < 8; ++f) {
                    int col = nt * 128 + wn * 64 + f * 8 + qc;
                    float2 gv = *(const float2*)(gcb + col);
                    float2 ov;
                    ov.x = acc[mf][f][rr * 2 + 0] + gv.x;
                    ov.y = acc[mf][f][rr * 2 + 1] + gv.y;
                    *(float2*)(fcb + col) = ov;
                }
            }
        }
    }
}

// ---- K4: 3xTF32 tensor-core einsum over flag-1 PAIRS; writes e and rev (transposed) ----
#define EIN_SMEM (8 * 4 * 576 * 4)
__global__ void __launch_bounds__(256) einsum_k() {
    extern __shared__ __align__(16) float esm[];
    int pcnt = d_pcnt;
    int t = threadIdx.x, warp = t >> 5, lane = t & 31;
    int p = blockIdx.x * 8 + warp;
    if (p >= pcnt) return;
    int e = d_plist[p];
    int g = e / EPG, ee = e - g * EPG;
    int rv = g * EPG + revloc(ee);
    float* sm0 = esm + warp * 2304;  // 4 matrices x 576 (16x36)
    const float* src0 = d_fc + e * 1024;
    const float* src1 = d_fc + rv * 1024;
#pragma unroll
    for (int i = 0; i < 8; ++i) {
        int j = i * 128 + lane * 4;
        int mat = j >> 9, a = (j >> 5) & 15, m = j & 31;
        float4 v0 = *(const float4*)(src0 + j);
        *(float4*)(sm0 + mat * 576 + a * 36 + m) = v0;
        float4 v1 = *(const float4*)(src1 + j);
        *(float4*)(sm0 + (mat + 2) * 576 + a * 36 + m) = v1;
    }
    __syncwarp();
    int r = lane >> 2, cb = lane & 3;
#pragma unroll
    for (int mat = 0; mat < 2; ++mat) {
        const float* Ae = sm0 + mat * 576;
        const float* Ar = sm0 + (mat + 2) * 576;
        float acc[2][4];
#pragma unroll
        for (int nf = 0; nf < 2; ++nf)
#pragma unroll
            for (int j = 0; j < 4; ++j) acc[nf][j] = 0.f;
#pragma unroll
        for (int ks = 0; ks < 4; ++ks) {
            const float* ap = Ae + r * 36 + ks * 8 + cb;
            float av[4] = {ap[0], ap[8 * 36], ap[4], ap[8 * 36 + 4]};
            uint32_t ah[4], al[4];
#pragma unroll
            for (int j = 0; j < 4; ++j) split_tf32(av[j], ah[j], al[j]);
#pragma unroll
            for (int nf = 0; nf < 2; ++nf) {
                const float* bp = Ar + (nf * 8 + r) * 36 + ks * 8 + cb;
                float b0f = bp[0], b1f = bp[4];
                uint32_t bh0, bl0, bh1, bl1;
                split_tf32(b0f, bh0, bl0);
                split_tf32(b1f, bh1, bl1);
                mma_tf32(acc[nf], ah, bh0, bh1);
                mma_tf32(acc[nf], ah, bl0, bl1);
                mma_tf32(acc[nf], al, bh0, bh1);
            }
        }
        float* fe = (mat ? d_uv : d_fv) + e * 256;
        float* fr = (mat ? d_uv : d_fv) + rv * 256;
#pragma unroll
        for (int nf = 0; nf < 2; ++nf) {
            int b = nf * 8 + cb * 2;
            *(float2*)(fe + r * 16 + b) = make_float2(acc[nf][0], acc[nf][1]);
            *(float2*)(fe + (r + 8) * 16 + b) = make_float2(acc[nf][2], acc[nf][3]);
            fr[b * 16 + r]           = acc[nf][0];
            fr[(b + 1) * 16 + r]     = acc[nf][1];
            fr[b * 16 + r + 8]       = acc[nf][2];
            fr[(b + 1) * 16 + r + 8] = acc[nf][3];
        }
    }
}

// ---- K5: BP, one CTA per graph, 512 threads, fv+uv cached; mean-centered messages ----
#define CAP 90
__global__ void __launch_bounds__(512) bp_k(float* __restrict__ out) {
    extern __shared__ __align__(16) float sm[];
    float* s_dat = sm;                     // CAP*512: per edge p: fv[256]|uv[256], swizzled
    float* sA   = sm + CAP * 512;          // 2112
    float* sB   = sA + 2112;
    float* uA   = sB + 2112;
    float* uB   = uA + 2112;
    float* s_mm = uB + 2112;               // 192
    float* s_um = s_mm + 192;
    float* s_if = s_um + 192;
    float* s_iu = s_if + 192;
    int*   s_act = (int*)(s_iu + 192);     // 132
    int*   s_cntp = s_act + 132;

    int g = blockIdx.x, t = threadIdx.x;
    if (t == 0) *s_cntp = 0;
    for (int i = t; i < 2112; i += 512) { sA[i] = 0.f; sB[i] = 0.f; uA[i] = 0.f; uB[i] = 0.f; }
    if (t < 192) {
        float fi = d_if[g * 192 + t], ui = d_iu[g * 192 + t];
        s_if[t] = fi; s_iu[t] = ui;
        s_mm[t] = fi; s_um[t] = ui;
    }
    __syncthreads();
    if (t < EPG && d_flag[g * EPG + t] != 0.f) {
        int p = atomicAdd(s_cntp, 1);
        s_act[p] = t;
    }
    __syncthreads();
    int cnt = *s_cntp;
    int cnt16 = cnt * 16;
    int lim = min(cnt, CAP);
    for (int i = t; i < lim * 128; i += 512) {
        int p = i >> 7, c = i & 127;
        int tens = c >> 6, cc = c & 63;
        int a = cc >> 2, q = cc & 3;
        int e = s_act[p];
        const float* src = (tens ? d_uv : d_fv) + (g * EPG + e) * 256 + cc * 4;
        float4 v = *(const float4*)src;
        int sw = a * 4 + (q ^ (a >> 2));
        *(float4*)(s_dat + p * 512 + tens * 256 + sw * 4) = v;
    }
    __syncthreads();

    for (int it = 0; it < NPG; ++it) {
        const float* om = (it & 1) ? sB : sA;
        const float* ou = (it & 1) ? uB : uA;
        float* nm = (it & 1) ? sA : sB;
        float* nu = (it & 1) ? uA : uB;
        for (int idx = t; idx < cnt16; idx += 512) {
            int p = idx >> 4;
            int e = s_act[p];
            int a = idx & 15;
            unsigned mask = (t & 16) ? 0xFFFF0000u : 0x0000FFFFu;
            int s = e / 11;
            int rev = revloc(e);
            float4 f0, f1, f2, f3, u0, u1, u2, u3;
            if (p < CAP) {
                const float* db = s_dat + p * 512;
                int ax4 = a * 4, ash = a >> 2;
                f0 = *(const float4*)(db + (ax4 + (0 ^ ash)) * 4);
                f1 = *(const float4*)(db + (ax4 + (1 ^ ash)) * 4);
                f2 = *(const float4*)(db + (ax4 + (2 ^ ash)) * 4);
                f3 = *(const float4*)(db + (ax4 + (3 ^ ash)) * 4);
                const float* ub = db + 256;
                u0 = *(const float4*)(ub + (ax4 + (0 ^ ash)) * 4);
                u1 = *(const float4*)(ub + (ax4 + (1 ^ ash)) * 4);
                u2 = *(const float4*)(ub + (ax4 + (2 ^ ash)) * 4);
                u3 = *(const float4*)(ub + (ax4 + (3 ^ ash)) * 4);
            } else {
                int ge = g * EPG + e;
                const float4* fvp = (const float4*)(d_fv + ge * 256 + a * 16);
                const float4* uvp = (const float4*)(d_uv + ge * 256 + a * 16);
                f0 = fvp[0]; f1 = fvp[1]; f2 = fvp[2]; f3 = fvp[3];
                u0 = uvp[0]; u1 = uvp[1]; u2 = uvp[2]; u3 = uvp[3];
            }
            float fv[16] = {f0.x, f0.y, f0.z, f0.w, f1.x, f1.y, f1.z, f1.w,
                            f2.x, f2.y, f2.z, f2.w, f3.x, f3.y, f3.z, f3.w};
            float uv[16] = {u0.x, u0.y, u0.z, u0.w, u1.x, u1.y, u1.z, u1.w,
                            u2.x, u2.y, u2.z, u2.w, u3.x, u3.y, u3.z, u3.w};
            float m[16], mx = -1e30f;
#pragma unroll
            for (int b = 0; b < 16; ++b) {
                float agg = s_mm[s * 16 + b] - om[rev * 16 + b];
                m[b] = fv[b] + agg;
                mx = fmaxf(mx, m[b]);
            }
            float se = 0.f;
#pragma unroll
            for (int b = 0; b < 16; ++b) {
                float pb = __expf(m[b] - mx);
                m[b] = pb;
                se += pb;
            }
            float lse = mx + __logf(se);
            // mean-centering over a (exactly equivalent to log-softmax for the final output)
            float ssum = lse;
#pragma unroll
            for (int w = 8; w > 0; w >>= 1) ssum += __shfl_xor_sync(mask, ssum, w);
            nm[e * 16 + a] = lse - ssum * 0.0625f;
            float acc = 0.f;
#pragma unroll
            for (int b = 0; b < 16; ++b) {
                float util = s_um[s * 16 + b] - ou[rev * 16 + b];
                acc += (uv[b] + util) * m[b];
            }
            nu[e * 16 + a] = acc * __fdividef(1.f, se);
        }
        __syncthreads();
        if (t < 192) {
            int n = t >> 4, b = t & 15;
            float am = 0.f, au = 0.f;
#pragma unroll
            for (int s2 = 0; s2 < NPG; ++s2) {
                if (s2 == n) continue;
                int ee = s2 * 11 + n - (n > s2);
                am += nm[ee * 16 + b];
                au += nu[ee * 16 + b];
            }
            s_mm[t] = am + s_if[t];
            s_um[t] = au + s_iu[t];
        }
        __syncthreads();
    }
    if (t < 16) out[g * 16 + t] = s_um[t];
}

#define BP_SMEM ((CAP * 512 + 4 * 2112 + 4 * 192) * 4 + 136 * 4)

extern "C" void kernel_launch(void* const* d_in, const int* in_sizes, int n_in,
                              void* d_out, int out_size) {
    const float* ef   = (const float*)d_in[0];
    const float* nf   = (const float*)d_in[1];
    const float* gf   = (const float*)d_in[2];
    const float* gn   = (const float*)d_in[7];
    const float* Wjf  = (const float*)d_in[8];
    const float* bjf  = (const float*)d_in[9];
    const float* Wif  = (const float*)d_in[10];
    const float* bif  = (const float*)d_in[11];
    const float* Wju  = (const float*)d_in[12];
    const float* bju  = (const float*)d_in[13];
    const float* Wiu  = (const float*)d_in[14];
    const float* biu  = (const float*)d_in[15];
    const float* Wfl  = (const float*)d_in[16];
    const float* bfl  = (const float*)d_in[17];
    const float* Wcls = (const float*)d_in[18];
    const float* bcls = (const float*)d_in[19];
    float* out = (float*)d_out;

    static int attr_set = 0;
    if (!attr_set) {
        cudaFuncSetAttribute(flvflag_k, cudaFuncAttributeMaxDynamicSharedMemorySize, FLV_SMEM);
        cudaFuncSetAttribute(gemm_k, cudaFuncAttributeMaxDynamicSharedMemorySize, GEMM_SMEM);
        cudaFuncSetAttribute(einsum_k, cudaFuncAttributeMaxDynamicSharedMemorySize, EIN_SMEM);
        cudaFuncSetAttribute(bp_k, cudaFuncAttributeMaxDynamicSharedMemorySize, BP_SMEM);
        attr_set = 1;
    }

    prep_k<<<1232, 256>>>(Wjf, bjf, Wju, bju, Wfl, bfl, gf, nf, Wif, bif, Wiu, biu);
    flvflag_k<<<B_, FLV_THREADS, FLV_SMEM>>>(ef, Wfl, gn, Wcls, bcls);
    gemm_k<<<dim3(8, 132), 256, GEMM_SMEM>>>(ef);
    einsum_k<<<1056, 256, EIN_SMEM>>>();
    bp_k<<<B_, 512, BP_SMEM>>>(out);
}

// round 11
// speedup vs baseline: 2.5218x; 1.0175x over previous
#include <cuda_runtime.h>
#include <cstdint>

#define B_    128
#define NPG   12
#define EPG   132
#define E_TOT 16896
#define NT    1536
#define NC    1056   // 512 jf | 512 ju | 32 fl (in d_gc)
#define CAP   90

__device__ float d_Wt[131072];         // tf32-prerounded, fragment-swizzled
__device__ float d_gc[B_ * NC];
__device__ float d_fc[E_TOT * 1024];   // slot-compacted per graph: (g*132+slot)*1024
__device__ float d_fv[E_TOT * 256];    // spill only (slot-indexed)
__device__ float d_uv[E_TOT * 256];
__device__ float d_if[NT * 16];
__device__ float d_iu[NT * 16];

__device__ __forceinline__ unsigned long long pk2(float lo, float hi) {
    unsigned long long r;
    asm("mov.b64 %0, {%1, %2};" : "=l"(r) : "f"(lo), "f"(hi));
    return r;
}
__device__ __forceinline__ void fma2(unsigned long long& d, unsigned long long a, unsigned long long b) {
    asm("fma.rn.f32x2 %0, %1, %2, %0;" : "+l"(d) : "l"(a), "l"(b));
}
__device__ __forceinline__ void up2(unsigned long long v, float& lo, float& hi) {
    asm("mov.b64 {%0, %1}, %2;" : "=f"(lo), "=f"(hi) : "l"(v));
}
__device__ __forceinline__ int revloc(int ee) {
    int s = ee / 11, dd = ee - s * 11;
    int d = dd + (dd >= s);
    return d * 11 + s - (s > d);
}
__device__ __forceinline__ void mma_tf32(float* d, const uint32_t* a, uint32_t b0, uint32_t b1) {
    asm volatile("mma.sync.aligned.m16n8k8.row.col.f32.tf32.tf32.f32 "
        "{%0,%1,%2,%3}, {%4,%5,%6,%7}, {%8,%9}, {%0,%1,%2,%3};\n"
        : "+f"(d[0]), "+f"(d[1]), "+f"(d[2]), "+f"(d[3])
        : "r"(a[0]), "r"(a[1]), "r"(a[2]), "r"(a[3]), "r"(b0), "r"(b1));
}
__device__ __forceinline__ uint32_t to_tf32(float v) {
    uint32_t r;
    asm("cvt.rna.tf32.f32 %0, %1;" : "=r"(r) : "f"(v));
    return r;
}
__device__ __forceinline__ void split_tf32(float v, uint32_t& hi, uint32_t& lo) {
    hi = to_tf32(v);
    lo = to_tf32(v - __uint_as_float(hi));
}

// ---- K1: fused prep: Wt pack (blocks 0..511) | gc (512..1039) | node lin (1040..1231) ----
__global__ void __launch_bounds__(256) prep_k(
        const float* __restrict__ Wjf, const float* __restrict__ bjf,
        const float* __restrict__ Wju, const float* __restrict__ bju,
        const float* __restrict__ Wfl, const float* __restrict__ bfl,
        const float* __restrict__ gf,  const float* __restrict__ nf,
        const float* __restrict__ Wif, const float* __restrict__ bif,
        const float* __restrict__ Wiu, const float* __restrict__ biu) {
    __shared__ float xn[8][128];
    int b = blockIdx.x, t = threadIdx.x;
    if (b < 512) {
        int i = b * 256 + t;
        int r = i & 1, f = (i >> 1) & 7, lane = (i >> 4) & 31;
        int wn = (i >> 9) & 1, ks = (i >> 10) & 15, nt = (i >> 14) & 7;
        int j = nt * 128 + wn * 64 + f * 8 + (lane >> 2);
        int k = ks * 8 + (lane & 3) + r * 4;
        float v = (j < 512) ? Wjf[k * 512 + j] : Wju[k * 512 + j - 512];
        d_Wt[i] = __uint_as_float(to_tf32(v));
    } else if (b < 1040) {
        int i = (b - 512) * 256 + t;
        int g = i / NC, j = i - g * NC;
        const float* Wp; int st; float acc;
        if (j < 512)        { Wp = Wjf + 128 * 512 + j;          st = 512; acc = bjf[j]; }
        else if (j < 1024)  { Wp = Wju + 128 * 512 + (j - 512);  st = 512; acc = bju[j - 512]; }
        else                { Wp = Wfl + 128 * 32  + (j - 1024); st = 32;  acc = bfl[j - 1024]; }
        const float* gr = gf + g * 64;
#pragma unroll 8
        for (int k = 0; k < 64; ++k) acc += gr[k] * Wp[k * st];
        d_gc[i] = acc;
    } else {
        int nb = (b - 1040) * 8;
        for (int i = t; i < 1024; i += 256) {
            int node = i >> 7, kk = i & 127;
            xn[node][kk] = (kk < 64) ? nf[(nb + node) * 64 + kk]
                                     : gf[((nb + node) / NPG) * 64 + kk - 64];
        }
        __syncthreads();
        int w = t >> 5, lane = t & 31;
        int n = nb + w;
        const float* W = (lane < 16) ? Wif : Wiu;
        int col = lane & 15;
        float acc = (lane < 16) ? bif[col] : biu[col];
#pragma unroll 8
        for (int k = 0; k < 128; ++k) acc += xn[w][k] * W[k * 16 + col];
        if (lane < 16) d_if[n * 16 + col] = acc;
        else           d_iu[n * 16 + col] = acc;
    }
}

// ---- K2: MEGA kernel — one CTA per graph does flv+flag+gemm+einsum+bp ----
// smem layout (floats):
//   [0, 46080)       big region: phase1-2: s_ef(17424)|s_W(4096)@17424|s_fl(4224)@21520|s_Wc(64)@25744
//                    phase3-4: s_dat = CAP*512 swizzled fv|uv
//   [46080, 54528)   sA|sB|uA|uB  (4 x 2112)
//   [54528, 55296)   s_mm|s_um|s_if|s_iu (4 x 192)
//   [55296, 55428)   s_act (132 ints)
//   [55428]          s_np
#define MEGA_SMEM (55432 * 4)
__global__ void __launch_bounds__(512, 1) mega_k(
        const float* __restrict__ ef, const float* __restrict__ Wfl,
        const float* __restrict__ noise, const float* __restrict__ Wc,
        const float* __restrict__ bc, float* __restrict__ out) {
    extern __shared__ __align__(16) float sm[];
    float* s_ef = sm;
    float* s_W  = sm + 17424;
    float* s_fl = sm + 21520;
    float* s_Wc = sm + 25744;
    float* s_dat = sm;
    float* sA = sm + 46080;
    float* sB = sA + 2112;
    float* uA = sB + 2112;
    float* uB = uA + 2112;
    float* s_mm = sm + 54528;
    float* s_um = sm + 54720;
    float* s_if = sm + 54912;
    float* s_iu = sm + 55104;
    int* s_act = (int*)(sm + 55296);
    int* s_np  = (int*)(sm + 55428);

    int g = blockIdx.x, t = threadIdx.x;
    if (t == 0) *s_np = 0;
    for (int i = t; i < 8448; i += 512) sA[i] = 0.f;
    if (t < 192) {
        float fi = d_if[g * 192 + t], ui = d_iu[g * 192 + t];
        s_if[t] = fi; s_iu[t] = ui;
        s_mm[t] = fi; s_um[t] = ui;
    }
    for (int i = t; i < 4224; i += 512) {
        int r = i >> 5, q = i & 31;
        float4 v = *(const float4*)(ef + (g * EPG + r) * 128 + q * 4);
        *(float4*)(s_ef + r * 132 + q * 4) = v;
    }
    for (int i = t; i < 1024; i += 512)
        *(float4*)(s_W + i * 4) = *(const float4*)(Wfl + i * 4);
    if (t < 64) s_Wc[t] = Wc[t];
    __syncthreads();

    // ---- Phase 1a: fl linear (264 threads: 2/edge x 16 cols) ----
    if (t < 264) {
        int e = t >> 1, co = (t & 1) * 16;
        unsigned long long acc[8];
        const float* gb = d_gc + g * NC + 1024 + co;
#pragma unroll
        for (int c = 0; c < 8; ++c) acc[c] = pk2(gb[c * 2], gb[c * 2 + 1]);
        const float* er = s_ef + e * 132;
#pragma unroll 4
        for (int k = 0; k < 128; ++k) {
            float a = er[k];
            unsigned long long aa = pk2(a, a);
            const float4* wr = (const float4*)(s_W + k * 32 + co);
            float4 w0 = wr[0], w1 = wr[1], w2 = wr[2], w3 = wr[3];
            fma2(acc[0], aa, pk2(w0.x, w0.y)); fma2(acc[1], aa, pk2(w0.z, w0.w));
            fma2(acc[2], aa, pk2(w1.x, w1.y)); fma2(acc[3], aa, pk2(w1.z, w1.w));
            fma2(acc[4], aa, pk2(w2.x, w2.y)); fma2(acc[5], aa, pk2(w2.z, w2.w));
            fma2(acc[6], aa, pk2(w3.x, w3.y)); fma2(acc[7], aa, pk2(w3.z, w3.w));
        }
        float* op = s_fl + e * 32 + co;
#pragma unroll
        for (int c = 0; c < 8; ++c) {
            float lo, hi;
            up2(acc[c], lo, hi);
            op[c * 2] = lo; op[c * 2 + 1] = hi;
        }
    }
    __syncthreads();

    // ---- Phase 1b: gumbel flags + pair-ordered active list ----
    if (t < EPG) {
        int e = t, rev = revloc(e);
        const float* pe = s_fl + e * 32;
        const float* pr = s_fl + rev * 32;
        float l0 = bc[0], l1 = bc[1];
#pragma unroll 8
        for (int c = 0; c < 32; ++c) {
            float p = pe[c] * pr[c];
            l0 += p * s_Wc[c * 2];
            l1 += p * s_Wc[c * 2 + 1];
        }
        int ge = g * EPG + e, grev = g * EPG + rev;
        int mn = min(ge, grev);
        float y0 = l0 + noise[2 * mn];
        float y1 = l1 + noise[2 * mn + 1];
        if (y0 >= y1 && e < rev) {
            int q = atomicAdd(s_np, 1);
            s_act[2 * q] = e;
            s_act[2 * q + 1] = rev;
        }
    }
    __syncthreads();
    int npairs = *s_np;
    int cnt = npairs * 2;

    // ---- Phase 2: tf32 GEMM for active edges: fc[slot] = ef[edge] @ W + gc ----
    {
        int lane = t & 31, warp = t >> 5;
        int nt = warp >> 1, wn = warp & 1;
        int nM = (cnt + 31) >> 5;
        const float* gcb = d_gc + g * NC;
        float* fcg = d_fc + (size_t)(g * 132) * 1024;
        int la = lane & 3;
        for (int mc = 0; mc < nM; ++mc) {
            float acc[2][8][4];
#pragma unroll
            for (int a = 0; a < 2; ++a)
#pragma unroll
                for (int f = 0; f < 8; ++f)
#pragma unroll
                    for (int j = 0; j < 4; ++j) acc[a][f][j] = 0.f;
            int rb = mc * 32 + (lane >> 2);
            int c1 = cnt - 1;
            const float* A0 = s_ef + s_act[min(rb, c1)] * 132 + la;
            const float* A1 = s_ef + s_act[min(rb + 8, c1)] * 132 + la;
            const float* A2 = s_ef + s_act[min(rb + 16, c1)] * 132 + la;
            const float* A3 = s_ef + s_act[min(rb + 24, c1)] * 132 + la;
            const float4* wt = (const float4*)d_Wt + (((nt * 16) * 2 + wn) * 32 + lane) * 4;
            float4 bq[4];
#pragma unroll
            for (int j = 0; j < 4; ++j) bq[j] = wt[j];
#pragma unroll
            for (int ks = 0; ks < 16; ++ks) {
                uint32_t br[16];
                br[0]  = __float_as_uint(bq[0].x); br[1]  = __float_as_uint(bq[0].y);
                br[2]  = __float_as_uint(bq[0].z); br[3]  = __float_as_uint(bq[0].w);
                br[4]  = __float_as_uint(bq[1].x); br[5]  = __float_as_uint(bq[1].y);
                br[6]  = __float_as_uint(bq[1].z); br[7]  = __float_as_uint(bq[1].w);
                br[8]  = __float_as_uint(bq[2].x); br[9]  = __float_as_uint(bq[2].y);
                br[10] = __float_as_uint(bq[2].z); br[11] = __float_as_uint(bq[2].w);
                br[12] = __float_as_uint(bq[3].x); br[13] = __float_as_uint(bq[3].y);
                br[14] = __float_as_uint(bq[3].z); br[15] = __float_as_uint(bq[3].w);
                if (ks < 15) {
                    const float4* nxt = wt + (ks + 1) * 256;
#pragma unroll
                    for (int j = 0; j < 4; ++j) bq[j] = nxt[j];
                }
                uint32_t a0[4], a1[4];
                a0[0] = to_tf32(A0[ks * 8]);     a0[1] = to_tf32(A1[ks * 8]);
                a0[2] = to_tf32(A0[ks * 8 + 4]); a0[3] = to_tf32(A1[ks * 8 + 4]);
                a1[0] = to_tf32(A2[ks * 8]);     a1[1] = to_tf32(A3[ks * 8]);
                a1[2] = to_tf32(A2[ks * 8 + 4]); a1[3] = to_tf32(A3[ks * 8 + 4]);
#pragma unroll
                for (int f = 0; f < 8; ++f) {
                    mma_tf32(acc[0][f], a0, br[f * 2], br[f * 2 + 1]);
                    mma_tf32(acc[1][f], a1, br[f * 2], br[f * 2 + 1]);
                }
            }
            int gr = lane >> 2, qc = la * 2;
#pragma unroll
            for (int mf = 0; mf < 2; ++mf) {
#pragma unroll
                for (int rr = 0; rr < 2; ++rr) {
                    int slot = mc * 32 + mf * 16 + gr + rr * 8;
                    if (slot < cnt) {
                        float* fcb = fcg + slot * 1024;
#pragma unroll
                        for (int f = 0; f < 8; ++f) {
                            int col = nt * 128 + wn * 64 + f * 8 + qc;
                            float2 gv = *(const float2*)(gcb + col);
                            float2 ov;
                            ov.x = acc[mf][f][rr * 2 + 0] + gv.x;
                            ov.y = acc[mf][f][rr * 2 + 1] + gv.y;
                            *(float2*)(fcb + col) = ov;
                        }
                    }
                }
            }
        }
    }
    __syncthreads();

    // ---- Phase 3: 3xTF32 einsum per pair, writes swizzled smem (spill to gmem) ----
    {
        int lane = t & 31, warp = t >> 5;
        int r = lane >> 2, cb = lane & 3;
        const float* fcg = d_fc + (size_t)(g * 132) * 1024;
        float* fvg = d_fv + (size_t)(g * 132) * 256;
        float* uvg = d_uv + (size_t)(g * 132) * 256;
        for (int p = warp; p < npairs; p += 16) {
            const float* fe = fcg + (2 * p) * 1024;
            const float* frp = fcg + (2 * p + 1) * 1024;
#pragma unroll
            for (int mat = 0; mat < 2; ++mat) {
                float acc[2][4];
#pragma unroll
                for (int nf = 0; nf < 2; ++nf)
#pragma unroll
                    for (int j = 0; j < 4; ++j) acc[nf][j] = 0.f;
#pragma unroll
                for (int ks = 0; ks < 4; ++ks) {
                    const float* ap = fe + mat * 512 + r * 32 + ks * 8 + cb;
                    float av[4] = {ap[0], ap[256], ap[4], ap[260]};
                    uint32_t ah[4], al[4];
#pragma unroll
                    for (int j = 0; j < 4; ++j) split_tf32(av[j], ah[j], al[j]);
#pragma unroll
                    for (int nf = 0; nf < 2; ++nf) {
                        const float* bp_ = frp + mat * 512 + (nf * 8 + r) * 32 + ks * 8 + cb;
                        float b0f = bp_[0], b1f = bp_[4];
                        uint32_t bh0, bl0, bh1, bl1;
                        split_tf32(b0f, bh0, bl0);
                        split_tf32(b1f, bh1, bl1);
                        mma_tf32(acc[nf], ah, bh0, bh1);
                        mma_tf32(acc[nf], ah, bl0, bl1);
                        mma_tf32(acc[nf], al, bh0, bh1);
                    }
                }
                float* gme = (mat ? uvg : fvg);
                int se = 2 * p, sr = 2 * p + 1;
#pragma unroll
                for (int nf = 0; nf < 2; ++nf) {
                    int b = nf * 8 + cb * 2;
                    int r8 = r + 8;
                    if (se < CAP) {
                        float* db = s_dat + se * 512 + mat * 256;
                        db[(r * 4 + ((b >> 2) ^ (r >> 2))) * 4 + (b & 3)] = acc[nf][0];
                        db[(r * 4 + (((b + 1) >> 2) ^ (r >> 2))) * 4 + ((b + 1) & 3)] = acc[nf][1];
                        db[(r8 * 4 + ((b >> 2) ^ (r8 >> 2))) * 4 + (b & 3)] = acc[nf][2];
                        db[(r8 * 4 + (((b + 1) >> 2) ^ (r8 >> 2))) * 4 + ((b + 1) & 3)] = acc[nf][3];
                    } else {
                        float* gp = gme + se * 256;
                        gp[r * 16 + b] = acc[nf][0];
                        gp[r * 16 + b + 1] = acc[nf][1];
                        gp[r8 * 16 + b] = acc[nf][2];
                        gp[r8 * 16 + b + 1] = acc[nf][3];
                    }
                    if (sr < CAP) {
                        float* db = s_dat + sr * 512 + mat * 256;
                        db[(b * 4 + ((r >> 2) ^ (b >> 2))) * 4 + (r & 3)] = acc[nf][0];
                        db[((b + 1) * 4 + ((r >> 2) ^ ((b + 1) >> 2))) * 4 + (r & 3)] = acc[nf][1];
                        db[(b * 4 + ((r8 >> 2) ^ (b >> 2))) * 4 + (r8 & 3)] = acc[nf][2];
                        db[((b + 1) * 4 + ((r8 >> 2) ^ ((b + 1) >> 2))) * 4 + (r8 & 3)] = acc[nf][3];
                    } else {
                        float* gp = gme + sr * 256;
                        gp[b * 16 + r] = acc[nf][0];
                        gp[(b + 1) * 16 + r] = acc[nf][1];
                        gp[b * 16 + r8] = acc[nf][2];
                        gp[(b + 1) * 16 + r8] = acc[nf][3];
                    }
                }
            }
        }
    }
    __syncthreads();

    // ---- Phase 4: BP iterations ----
    {
        const float* fvg = d_fv + (size_t)(g * 132) * 256;
        const float* uvg = d_uv + (size_t)(g * 132) * 256;
        int cnt16 = cnt * 16;
        for (int it = 0; it < NPG; ++it) {
            const float* om = (it & 1) ? sB : sA;
            const float* ou = (it & 1) ? uB : uA;
            float* nm = (it & 1) ? sA : sB;
            float* nu = (it & 1) ? uA : uB;
            for (int idx = t; idx < cnt16; idx += 512) {
                int p = idx >> 4;
                int e = s_act[p];
                int a = idx & 15;
                unsigned mask = (t & 16) ? 0xFFFF0000u : 0x0000FFFFu;
                int s = e / 11;
                int rev = revloc(e);
                float4 f0, f1, f2, f3, u0, u1, u2, u3;
                if (p < CAP) {
                    const float* db = s_dat + p * 512;
                    int ax4 = a * 4, ash = a >> 2;
                    f0 = *(const float4*)(db + (ax4 + (0 ^ ash)) * 4);
                    f1 = *(const float4*)(db + (ax4 + (1 ^ ash)) * 4);
                    f2 = *(const float4*)(db + (ax4 + (2 ^ ash)) * 4);
                    f3 = *(const float4*)(db + (ax4 + (3 ^ ash)) * 4);
                    const float* ub = db + 256;
                    u0 = *(const float4*)(ub + (ax4 + (0 ^ ash)) * 4);
                    u1 = *(const float4*)(ub + (ax4 + (1 ^ ash)) * 4);
                    u2 = *(const float4*)(ub + (ax4 + (2 ^ ash)) * 4);
                    u3 = *(const float4*)(ub + (ax4 + (3 ^ ash)) * 4);
                } else {
                    const float4* fvp = (const float4*)(fvg + p * 256 + a * 16);
                    const float4* uvp = (const float4*)(uvg + p * 256 + a * 16);
                    f0 = fvp[0]; f1 = fvp[1]; f2 = fvp[2]; f3 = fvp[3];
                    u0 = uvp[0]; u1 = uvp[1]; u2 = uvp[2]; u3 = uvp[3];
                }
                float fv[16] = {f0.x, f0.y, f0.z, f0.w, f1.x, f1.y, f1.z, f1.w,
                                f2.x, f2.y, f2.z, f2.w, f3.x, f3.y, f3.z, f3.w};
                float uv[16] = {u0.x, u0.y, u0.z, u0.w, u1.x, u1.y, u1.z, u1.w,
                                u2.x, u2.y, u2.z, u2.w, u3.x, u3.y, u3.z, u3.w};
                float m[16], mx = -1e30f;
#pragma unroll
                for (int b = 0; b < 16; ++b) {
                    float agg = s_mm[s * 16 + b] - om[rev * 16 + b];
                    m[b] = fv[b] + agg;
                    mx = fmaxf(mx, m[b]);
                }
                float se = 0.f;
#pragma unroll
                for (int b = 0; b < 16; ++b) {
                    float pb = __expf(m[b] - mx);
                    m[b] = pb;
                    se += pb;
                }
                float lse = mx + __logf(se);
                float ssum = lse;
#pragma unroll
                for (int w = 8; w > 0; w >>= 1) ssum += __shfl_xor_sync(mask, ssum, w);
                nm[e * 16 + a] = lse - ssum * 0.0625f;
                float acc = 0.f;
#pragma unroll
                for (int b = 0; b < 16; ++b) {
                    float util = s_um[s * 16 + b] - ou[rev * 16 + b];
                    acc += (uv[b] + util) * m[b];
                }
                nu[e * 16 + a] = acc * __fdividef(1.f, se);
            }
            __syncthreads();
            if (t < 192) {
                int n = t >> 4, b = t & 15;
                float am = 0.f, au = 0.f;
#pragma unroll
                for (int s2 = 0; s2 < NPG; ++s2) {
                    if (s2 == n) continue;
                    int ee = s2 * 11 + n - (n > s2);
                    am += nm[ee * 16 + b];
                    au += nu[ee * 16 + b];
                }
                s_mm[t] = am + s_if[t];
                s_um[t] = au + s_iu[t];
            }
            __syncthreads();
        }
    }
    if (t < 16) out[g * 16 + t] = s_um[t];
}

extern "C" void kernel_launch(void* const* d_in, const int* in_sizes, int n_in,
                              void* d_out, int out_size) {
    const float* ef   = (const float*)d_in[0];
    const float* nf   = (const float*)d_in[1];
    const float* gf   = (const float*)d_in[2];
    const float* gn   = (const float*)d_in[7];
    const float* Wjf  = (const float*)d_in[8];
    const float* bjf  = (const float*)d_in[9];
    const float* Wif  = (const float*)d_in[10];
    const float* bif  = (const float*)d_in[11];
    const float* Wju  = (const float*)d_in[12];
    const float* bju  = (const float*)d_in[13];
    const float* Wiu  = (const float*)d_in[14];
    const float* biu  = (const float*)d_in[15];
    const float* Wfl  = (const float*)d_in[16];
    const float* bfl  = (const float*)d_in[17];
    const float* Wcls = (const float*)d_in[18];
    const float* bcls = (const float*)d_in[19];
    float* out = (float*)d_out;

    static int attr_set = 0;
    if (!attr_set) {
        cudaFuncSetAttribute(mega_k, cudaFuncAttributeMaxDynamicSharedMemorySize, MEGA_SMEM);
        attr_set = 1;
    }

    prep_k<<<1232, 256>>>(Wjf, bjf, Wju, bju, Wfl, bfl, gf, nf, Wif, bif, Wiu, biu);
    mega_k<<<B_, 512, MEGA_SMEM>>>(ef, Wfl, gn, Wcls, bcls, out);
}